// round 10
// baseline (speedup 1.0000x reference)
#include <cuda_runtime.h>
#include <cuda_bf16.h>
#include <cstdint>
#include <math.h>

// Problem constants
#define BB 2
#define SS 2048
#define DD 1280
#define HH 16
#define DP 80
#define MROWS (BB * SS)          // 4096
#define NQKV (3 * DD)            // 3840

// ---------------------------------------------------------------------------
// Device scratch (allocation-free rule)
// ---------------------------------------------------------------------------
__device__ __nv_bfloat16 g_Qhi[BB * HH * SS * DP];
__device__ __nv_bfloat16 g_Qlo[BB * HH * SS * DP];
__device__ __nv_bfloat16 g_Khi[BB * HH * SS * DP];
__device__ __nv_bfloat16 g_Klo[BB * HH * SS * DP];
__device__ __nv_bfloat16 g_Vhi[BB * HH * SS * DP];
__device__ __nv_bfloat16 g_Vlo[BB * HH * SS * DP];

__device__ __nv_bfloat16 g_Xhi[MROWS * DD];
__device__ __nv_bfloat16 g_Xlo[MROWS * DD];
__device__ __nv_bfloat16 g_WThi[4 * DD * DD];   // rows [0,3840)=Wq,Wk,Wv^T ; [3840,5120)=Wo^T
__device__ __nv_bfloat16 g_WTlo[4 * DD * DD];
__device__ __nv_bfloat16 g_Chi[MROWS * DD];
__device__ __nv_bfloat16 g_Clo[MROWS * DD];

// ---------------------------------------------------------------------------
// mma.sync + ldmatrix + cp.async helpers (portable to sm_103)
// ---------------------------------------------------------------------------
__device__ __forceinline__ void mma16816(float* c, const uint32_t* a, const uint32_t* b) {
    asm volatile(
        "mma.sync.aligned.m16n8k16.row.col.f32.bf16.bf16.f32 "
        "{%0,%1,%2,%3}, {%4,%5,%6,%7}, {%8,%9}, {%0,%1,%2,%3};"
        : "+f"(c[0]), "+f"(c[1]), "+f"(c[2]), "+f"(c[3])
        : "r"(a[0]), "r"(a[1]), "r"(a[2]), "r"(a[3]), "r"(b[0]), "r"(b[1]));
}

__device__ __forceinline__ void ldsm_x4(uint32_t* r, uint32_t addr) {
    asm volatile("ldmatrix.sync.aligned.m8n8.x4.shared.b16 {%0,%1,%2,%3}, [%4];"
        : "=r"(r[0]), "=r"(r[1]), "=r"(r[2]), "=r"(r[3]) : "r"(addr));
}
__device__ __forceinline__ void ldsm_x4_t(uint32_t* r, uint32_t addr) {
    asm volatile("ldmatrix.sync.aligned.m8n8.x4.trans.shared.b16 {%0,%1,%2,%3}, [%4];"
        : "=r"(r[0]), "=r"(r[1]), "=r"(r[2]), "=r"(r[3]) : "r"(addr));
}

__device__ __forceinline__ uint32_t smem_u32(const void* p) {
    return (uint32_t)__cvta_generic_to_shared(p);
}

__device__ __forceinline__ void cp_async16(uint32_t dst, const void* src) {
    asm volatile("cp.async.ca.shared.global [%0], [%1], 16;" :: "r"(dst), "l"(src));
}
__device__ __forceinline__ void cp_commit() {
    asm volatile("cp.async.commit_group;");
}

// split a,b -> packed bf16x2 hi and lo
__device__ __forceinline__ void split_pack2(float a, float b, uint32_t& hi, uint32_t& lo) {
    __nv_bfloat16 ha = __float2bfloat16(a), hb = __float2bfloat16(b);
    __nv_bfloat16 la = __float2bfloat16(a - __bfloat162float(ha));
    __nv_bfloat16 lb = __float2bfloat16(b - __bfloat162float(hb));
    __nv_bfloat162 H = __nv_bfloat162(ha, hb);
    __nv_bfloat162 L = __nv_bfloat162(la, lb);
    hi = *(uint32_t*)&H;
    lo = *(uint32_t*)&L;
}

// ---------------------------------------------------------------------------
// fp32 -> (bf16 hi, bf16 lo) elementwise split
// ---------------------------------------------------------------------------
__global__ __launch_bounds__(256) void split_kernel(const float* __restrict__ src,
                                                    __nv_bfloat16* __restrict__ hi,
                                                    __nv_bfloat16* __restrict__ lo,
                                                    int n2) {
    int i = blockIdx.x * blockDim.x + threadIdx.x;
    if (i >= n2) return;
    float2 v = *(const float2*)(src + 2 * (size_t)i);
    __nv_bfloat16 h0 = __float2bfloat16(v.x);
    __nv_bfloat16 h1 = __float2bfloat16(v.y);
    __nv_bfloat16 l0 = __float2bfloat16(v.x - __bfloat162float(h0));
    __nv_bfloat16 l1 = __float2bfloat16(v.y - __bfloat162float(h1));
    *(__nv_bfloat162*)(hi + 2 * (size_t)i) = __nv_bfloat162(h0, h1);
    *(__nv_bfloat162*)(lo + 2 * (size_t)i) = __nv_bfloat162(l0, l1);
}

// ---------------------------------------------------------------------------
// W [K=1280, N=1280] row-major -> W^T split; blockIdx.z selects matrix
// ---------------------------------------------------------------------------
__global__ __launch_bounds__(256) void wsplit4_kernel(const float* __restrict__ W0,
                                                      const float* __restrict__ W1,
                                                      const float* __restrict__ W2,
                                                      const float* __restrict__ W3) {
    __shared__ float tile[32][33];
    const int z  = blockIdx.z;
    const float* W = (z == 0) ? W0 : (z == 1) ? W1 : (z == 2) ? W2 : W3;
    const int ro = z * DD;
    const int tx = threadIdx.x;
    const int ty = threadIdx.y;
    const int n0 = blockIdx.x * 32;
    const int k0 = blockIdx.y * 32;
#pragma unroll
    for (int q = 0; q < 4; q++)
        tile[ty + q * 8][tx] = W[(size_t)(k0 + ty + q * 8) * DD + n0 + tx];
    __syncthreads();
#pragma unroll
    for (int q = 0; q < 4; q++) {
        const int nn = n0 + ty + q * 8;
        const int kk = k0 + tx;
        float v = tile[tx][ty + q * 8];
        __nv_bfloat16 h = __float2bfloat16(v);
        __nv_bfloat16 l = __float2bfloat16(v - __bfloat162float(h));
        g_WThi[(size_t)(ro + nn) * DD + kk] = h;
        g_WTlo[(size_t)(ro + nn) * DD + kk] = l;
    }
}

// ---------------------------------------------------------------------------
// HMMA split-bf16 GEMM v2: 256x128 tile, 512 threads, 2-stage cp.async,
// ldmatrix feeds, smem-staged coalesced epilogue (mode 0).
// ---------------------------------------------------------------------------
#define BK2 32
#define AP 40                         // smem pitch bf16 (80B rows)
#define STG_BF16 (768 * AP)           // (256+256+128+128) rows x 40
#define OFF_ALO (256 * AP)
#define OFF_BHI (512 * AP)
#define OFF_BLO (640 * AP)
#define GEMM_SMEM_BYTES (2 * STG_BF16 * 2)   // 122880 B

__global__ __launch_bounds__(512, 1) void mma_gemm_kernel(
    const __nv_bfloat16* __restrict__ Ahi, const __nv_bfloat16* __restrict__ Alo,
    const __nv_bfloat16* __restrict__ Bhi, const __nv_bfloat16* __restrict__ Blo,
    const float* __restrict__ b0, const float* __restrict__ b1, const float* __restrict__ b2,
    int mode, float* __restrict__ outp)
{
    extern __shared__ __nv_bfloat16 dsm[];

    const int t    = threadIdx.x;
    const int wid  = t >> 5;
    const int lane = t & 31;
    const int n0   = blockIdx.x * 128;
    const int m0   = blockIdx.y * 256;
    const int wm   = (wid >> 2) * 64;     // 0,64,128,192
    const int wn   = (wid & 3) * 32;
    const int g    = lane >> 2;
    const int t4   = lane & 3;

    const int a_r = (lane & 7) + ((lane >> 3) & 1) * 8;
    const int a_c = (lane >> 4) * 8;
    const int b_r = (lane & 7) + ((lane >> 4) & 1) * 8;
    const int b_c = ((lane >> 3) & 1) * 8;

    const uint32_t sbase = smem_u32(dsm);

    // cp.async thread mapping
    const int arow = t >> 1;              // 0..255
    const int acol = (t & 1) * 16;        // bf16 col base (two 16B ops)
    const int brow = t >> 2;              // 0..127
    const int bc16 = t & 3;               // one 16B op

    const __nv_bfloat16* pAhi = Ahi + (size_t)(m0 + arow) * DD + acol;
    const __nv_bfloat16* pAlo = Alo + (size_t)(m0 + arow) * DD + acol;
    const __nv_bfloat16* pBhi = Bhi + (size_t)(n0 + brow) * DD + bc16 * 8;
    const __nv_bfloat16* pBlo = Blo + (size_t)(n0 + brow) * DD + bc16 * 8;
    const uint32_t adst = (uint32_t)((arow * AP + acol) * 2);
    const uint32_t bdst = (uint32_t)((brow * AP) * 2 + bc16 * 16);

    float acc[4][4][4];
#pragma unroll
    for (int mi = 0; mi < 4; mi++)
#pragma unroll
        for (int ni = 0; ni < 4; ni++)
#pragma unroll
            for (int q = 0; q < 4; q++) acc[mi][ni][q] = 0.f;

    const int KCH = DD / BK2;       // 40

    // prologue: stage 0 <- chunk 0
    {
        const uint32_t sb = sbase;
        cp_async16(sb + adst,                        pAhi);
        cp_async16(sb + adst + 16,                   pAhi + 8);
        cp_async16(sb + OFF_ALO * 2 + adst,          pAlo);
        cp_async16(sb + OFF_ALO * 2 + adst + 16,     pAlo + 8);
        cp_async16(sb + OFF_BHI * 2 + bdst,          pBhi);
        cp_async16(sb + OFF_BLO * 2 + bdst,          pBlo);
        cp_commit();
    }

    for (int kc = 0; kc < KCH; kc++) {
        if (kc + 1 < KCH) {
            const int kk = (kc + 1) * BK2;
            const uint32_t sb = sbase + (uint32_t)(((kc + 1) & 1) * STG_BF16 * 2);
            cp_async16(sb + adst,                        pAhi + kk);
            cp_async16(sb + adst + 16,                   pAhi + kk + 8);
            cp_async16(sb + OFF_ALO * 2 + adst,          pAlo + kk);
            cp_async16(sb + OFF_ALO * 2 + adst + 16,     pAlo + kk + 8);
            cp_async16(sb + OFF_BHI * 2 + bdst,          pBhi + kk);
            cp_async16(sb + OFF_BLO * 2 + bdst,          pBlo + kk);
            cp_commit();
            asm volatile("cp.async.wait_group 1;");
        } else {
            asm volatile("cp.async.wait_group 0;");
        }
        __syncthreads();

        const uint32_t st = sbase + (uint32_t)((kc & 1) * STG_BF16 * 2);
        const uint32_t uAhi = st;
        const uint32_t uAlo = st + OFF_ALO * 2;
        const uint32_t uBhi = st + OFF_BHI * 2;
        const uint32_t uBlo = st + OFF_BLO * 2;

#pragma unroll
        for (int ks = 0; ks < 2; ks++) {
            const int kb = ks * 16;
            uint32_t bh[4][2], bl[4][2];
#pragma unroll
            for (int p = 0; p < 2; p++) {
                const uint32_t off = (uint32_t)(((wn + p * 16 + b_r) * AP + kb + b_c) * 2);
                uint32_t r4[4];
                ldsm_x4(r4, uBhi + off);
                bh[2 * p][0] = r4[0]; bh[2 * p][1] = r4[1];
                bh[2 * p + 1][0] = r4[2]; bh[2 * p + 1][1] = r4[3];
                ldsm_x4(r4, uBlo + off);
                bl[2 * p][0] = r4[0]; bl[2 * p][1] = r4[1];
                bl[2 * p + 1][0] = r4[2]; bl[2 * p + 1][1] = r4[3];
            }
#pragma unroll
            for (int mi = 0; mi < 4; mi++) {
                const uint32_t off = (uint32_t)(((wm + mi * 16 + a_r) * AP + kb + a_c) * 2);
                uint32_t ah[4], al[4];
                ldsm_x4(ah, uAhi + off);
                ldsm_x4(al, uAlo + off);
#pragma unroll
                for (int ni = 0; ni < 4; ni++) {
                    mma16816(acc[mi][ni], ah, bh[ni]);
                    mma16816(acc[mi][ni], ah, bl[ni]);
                    mma16816(acc[mi][ni], al, bh[ni]);
                }
            }
        }
        __syncthreads();
    }

    if (mode == 0) {
        // which (Q/K/V) is uniform per CTA: tile width 128 divides 1280
        const int which = n0 / DD;
        const int nl0   = n0 - which * DD;
        const float* bias = (which == 0) ? b0 : (which == 1) ? b1 : b2;
        __nv_bfloat16* dsth = (which == 0) ? g_Qhi : (which == 1) ? g_Khi : g_Vhi;
        __nv_bfloat16* dstl = (which == 0) ? g_Qlo : (which == 1) ? g_Klo : g_Vlo;

        // two passes: stage hi plane then lo plane in smem (256x128 bf16 = 64KB)
#pragma unroll
        for (int pass = 0; pass < 2; pass++) {
            __syncthreads();
#pragma unroll
            for (int mi = 0; mi < 4; mi++) {
#pragma unroll
                for (int ni = 0; ni < 4; ni++) {
#pragma unroll
                    for (int q = 0; q < 4; q++) {
                        const int rl = wm + mi * 16 + g + (q >> 1) * 8;
                        const int cl = wn + ni * 8 + t4 * 2 + (q & 1);
                        const float val = acc[mi][ni][q] + bias[nl0 + cl];
                        const __nv_bfloat16 hv = __float2bfloat16(val);
                        dsm[rl * 128 + cl] = pass
                            ? __float2bfloat16(val - __bfloat162float(hv)) : hv;
                    }
                }
            }
            __syncthreads();
            __nv_bfloat16* dst = pass ? dstl : dsth;
#pragma unroll
            for (int i = 0; i < 32; i++) {
                const int idx = t + i * 512;       // 0..16383
                const int row = idx >> 6;
                const int pc  = idx & 63;
                const int cl  = nl0 + pc * 2;
                const int head = cl / DP;
                const int dd   = cl - head * DP;
                const int grow = m0 + row;
                const int b_ = grow >> 11;
                const int s_ = grow & 2047;
                const size_t o = (((size_t)b_ * HH + head) * SS + s_) * DP + dd;
                *(uint32_t*)&dst[o] = *(uint32_t*)&dsm[row * 128 + pc * 2];
            }
        }
    } else {
        // fp32 direct epilogue
#pragma unroll
        for (int mi = 0; mi < 4; mi++) {
            const int r0 = m0 + wm + mi * 16 + g;
#pragma unroll
            for (int ni = 0; ni < 4; ni++) {
                const int cg0 = n0 + wn + ni * 8 + t4 * 2;
#pragma unroll
                for (int q = 0; q < 4; q++) {
                    const int row = r0 + (q >> 1) * 8;
                    const int cg  = cg0 + (q & 1);
                    outp[(size_t)row * DD + cg] = acc[mi][ni][q] + b0[cg];
                }
            }
        }
    }
}

// ---------------------------------------------------------------------------
// HMMA flash attention: 256 q-rows/CTA, 512 threads (16 warps x 16 rows),
// 64-key tiles with 2-stage cp.async double-buffered K/V pipeline.
// ---------------------------------------------------------------------------
#define QP 88                       // smem pitch bf16 (176B rows)
#define QROWS 256
#define KVSTG (4 * 64 * QP)         // bf16 per K/V stage (Kh,Kl,Vh,Vl)
#define ATT_SMEM_BYTES ((2 * QROWS * QP + 2 * KVSTG) * 2)

__global__ __launch_bounds__(512, 1) void attn_mma_kernel()
{
    extern __shared__ __nv_bfloat16 sm[];
    __nv_bfloat16* sQh = sm;
    __nv_bfloat16* sQl = sm + QROWS * QP;

    const int t    = threadIdx.x;
    const int wid  = t >> 5;
    const int lane = t & 31;
    const int g    = lane >> 2;
    const int t4   = lane & 3;
    const int idx   = blockIdx.x;            // 0..255
    const int qt    = 7 - (idx >> 5);        // 8 q-tiles, big first
    const int hb    = idx & 31;
    const int h     = hb & 15;
    const int b     = hb >> 4;
    const size_t bh_off = ((size_t)b * HH + h) * SS * DP;
    const int qbase = qt * QROWS;
    const int wm    = wid * 16;
    const float scale = 0.11180339887498948f;   // 1/sqrt(80)

    const int a_r = (lane & 7) + ((lane >> 3) & 1) * 8;
    const int a_c = (lane >> 4) * 8;
    const int b_r = (lane & 7) + ((lane >> 4) & 1) * 8;
    const int b_c = ((lane >> 3) & 1) * 8;
    const int v_r = (lane & 7) + ((lane >> 3) & 1) * 8;
    const int v_c = ((lane >> 4) & 1) * 8;

    const uint32_t uQh = smem_u32(sQh), uQl = smem_u32(sQl);
    const uint32_t uKV = smem_u32(sm + 2 * QROWS * QP);

    const int ktiles = 4 * qt + 4;

    // Prologue: Q tile (256x80 hi+lo) + K/V tile 0, one cp.async group
    {
        const size_t qbyte = (bh_off + (size_t)qbase * DP) * 2;
        const char* qh = (const char*)g_Qhi + qbyte;
        const char* ql = (const char*)g_Qlo + qbyte;
#pragma unroll
        for (int it = 0; it < 10; it++) {
            const int id2 = t + it * 512;
            const int arr = id2 / 2560;
            const int rem = id2 - arr * 2560;
            const int row = rem / 10;
            const int c16 = rem - row * 10;
            cp_async16((arr ? uQl : uQh) + (uint32_t)(row * (QP * 2) + c16 * 16),
                       (arr ? ql : qh) + (size_t)row * (DP * 2) + c16 * 16);
        }
        const size_t kbyte = bh_off * 2;
        const char* srcs[4] = {
            (const char*)g_Khi + kbyte, (const char*)g_Klo + kbyte,
            (const char*)g_Vhi + kbyte, (const char*)g_Vlo + kbyte };
#pragma unroll
        for (int it = 0; it < 5; it++) {
            const int id2 = t + it * 512;
            const int arr = id2 / 640;
            const int rem = id2 - arr * 640;
            const int row = rem / 10;
            const int c16 = rem - row * 10;
            cp_async16(uKV + (uint32_t)(arr * (64 * QP * 2) + row * (QP * 2) + c16 * 16),
                       srcs[arr] + (size_t)row * (DP * 2) + c16 * 16);
        }
        cp_commit();
    }

    float oacc[10][4];
#pragma unroll
    for (int nj = 0; nj < 10; nj++)
#pragma unroll
        for (int q = 0; q < 4; q++) oacc[nj][q] = 0.f;
    float m0 = -1e30f, m1 = -1e30f, l0 = 0.f, l1 = 0.f;

    const int gr0 = qbase + wm + g;
    const int gr1 = gr0 + 8;

    for (int kb = 0; kb < ktiles; kb++) {
        if (kb + 1 < ktiles) {
            const size_t kbyte = (bh_off + (size_t)(kb + 1) * 64 * DP) * 2;
            const char* srcs[4] = {
                (const char*)g_Khi + kbyte, (const char*)g_Klo + kbyte,
                (const char*)g_Vhi + kbyte, (const char*)g_Vlo + kbyte };
            const uint32_t dstb = uKV + (uint32_t)(((kb + 1) & 1) * KVSTG * 2);
#pragma unroll
            for (int it = 0; it < 5; it++) {
                const int id2 = t + it * 512;
                const int arr = id2 / 640;
                const int rem = id2 - arr * 640;
                const int row = rem / 10;
                const int c16 = rem - row * 10;
                cp_async16(dstb + (uint32_t)(arr * (64 * QP * 2) + row * (QP * 2) + c16 * 16),
                           srcs[arr] + (size_t)row * (DP * 2) + c16 * 16);
            }
            cp_commit();
            asm volatile("cp.async.wait_group 1;");
        } else {
            asm volatile("cp.async.wait_group 0;");
        }
        __syncthreads();

        const uint32_t stb = uKV + (uint32_t)((kb & 1) * KVSTG * 2);
        const uint32_t uKh = stb;
        const uint32_t uKl = stb + (uint32_t)(64 * QP * 2);
        const uint32_t uVh = stb + (uint32_t)(2 * 64 * QP * 2);
        const uint32_t uVl = stb + (uint32_t)(3 * 64 * QP * 2);

        // S = Q @ K^T
        float sacc[8][4];
#pragma unroll
        for (int ni = 0; ni < 8; ni++)
#pragma unroll
            for (int q = 0; q < 4; q++) sacc[ni][q] = 0.f;

#pragma unroll
        for (int kc = 0; kc < 5; kc++) {
            const int ko = kc * 16;
            uint32_t ah[4], al[4];
            ldsm_x4(ah, uQh + (uint32_t)(((wm + a_r) * QP + ko + a_c) * 2));
            ldsm_x4(al, uQl + (uint32_t)(((wm + a_r) * QP + ko + a_c) * 2));
#pragma unroll
            for (int p = 0; p < 4; p++) {
                const uint32_t off = (uint32_t)(((p * 16 + b_r) * QP + ko + b_c) * 2);
                uint32_t rh[4], rl[4];
                ldsm_x4(rh, uKh + off);
                ldsm_x4(rl, uKl + off);
                mma16816(sacc[2 * p],     ah, rh);
                mma16816(sacc[2 * p],     ah, rl);
                mma16816(sacc[2 * p],     al, rh);
                mma16816(sacc[2 * p + 1], ah, rh + 2);
                mma16816(sacc[2 * p + 1], ah, rl + 2);
                mma16816(sacc[2 * p + 1], al, rh + 2);
            }
        }

        // scale + causal mask (additive -10000, matches reference)
        const bool edge = (kb >= 4 * qt);
#pragma unroll
        for (int ni = 0; ni < 8; ni++) {
#pragma unroll
            for (int q = 0; q < 4; q++) {
                float v = sacc[ni][q] * scale;
                if (edge) {
                    const int key = kb * 64 + ni * 8 + t4 * 2 + (q & 1);
                    const int qr  = (q < 2) ? gr0 : gr1;
                    if (key > qr) v -= 10000.f;
                }
                sacc[ni][q] = v;
            }
        }

        // online softmax
        float mx0 = -1e30f, mx1 = -1e30f;
#pragma unroll
        for (int ni = 0; ni < 8; ni++) {
            mx0 = fmaxf(mx0, fmaxf(sacc[ni][0], sacc[ni][1]));
            mx1 = fmaxf(mx1, fmaxf(sacc[ni][2], sacc[ni][3]));
        }
        mx0 = fmaxf(mx0, __shfl_xor_sync(0xffffffffu, mx0, 1));
        mx0 = fmaxf(mx0, __shfl_xor_sync(0xffffffffu, mx0, 2));
        mx1 = fmaxf(mx1, __shfl_xor_sync(0xffffffffu, mx1, 1));
        mx1 = fmaxf(mx1, __shfl_xor_sync(0xffffffffu, mx1, 2));
        const float mn0 = fmaxf(m0, mx0), mn1 = fmaxf(m1, mx1);
        const float c0 = __expf(m0 - mn0), c1 = __expf(m1 - mn1);
        float s0 = 0.f, s1 = 0.f;
#pragma unroll
        for (int ni = 0; ni < 8; ni++) {
            sacc[ni][0] = __expf(sacc[ni][0] - mn0);
            sacc[ni][1] = __expf(sacc[ni][1] - mn0);
            sacc[ni][2] = __expf(sacc[ni][2] - mn1);
            sacc[ni][3] = __expf(sacc[ni][3] - mn1);
            s0 += sacc[ni][0] + sacc[ni][1];
            s1 += sacc[ni][2] + sacc[ni][3];
        }
        s0 += __shfl_xor_sync(0xffffffffu, s0, 1);
        s0 += __shfl_xor_sync(0xffffffffu, s0, 2);
        s1 += __shfl_xor_sync(0xffffffffu, s1, 1);
        s1 += __shfl_xor_sync(0xffffffffu, s1, 2);
        l0 = l0 * c0 + s0;  m0 = mn0;
        l1 = l1 * c1 + s1;  m1 = mn1;

#pragma unroll
        for (int nj = 0; nj < 10; nj++) {
            oacc[nj][0] *= c0; oacc[nj][1] *= c0;
            oacc[nj][2] *= c1; oacc[nj][3] *= c1;
        }

        // O += P @ V  (P in regs; V^T fragments via ldmatrix.trans)
#pragma unroll
        for (int kc2 = 0; kc2 < 4; kc2++) {
            uint32_t aph[4], apl[4];
            split_pack2(sacc[2 * kc2][0],     sacc[2 * kc2][1],     aph[0], apl[0]);
            split_pack2(sacc[2 * kc2][2],     sacc[2 * kc2][3],     aph[1], apl[1]);
            split_pack2(sacc[2 * kc2 + 1][0], sacc[2 * kc2 + 1][1], aph[2], apl[2]);
            split_pack2(sacc[2 * kc2 + 1][2], sacc[2 * kc2 + 1][3], aph[3], apl[3]);
            const int ko2 = kc2 * 16;
#pragma unroll
            for (int p = 0; p < 5; p++) {
                const uint32_t off = (uint32_t)(((ko2 + v_r) * QP + p * 16 + v_c) * 2);
                uint32_t rh[4], rl[4];
                ldsm_x4_t(rh, uVh + off);
                ldsm_x4_t(rl, uVl + off);
                mma16816(oacc[2 * p],     aph, rh);
                mma16816(oacc[2 * p],     aph, rl);
                mma16816(oacc[2 * p],     apl, rh);
                mma16816(oacc[2 * p + 1], aph, rh + 2);
                mma16816(oacc[2 * p + 1], aph, rl + 2);
                mma16816(oacc[2 * p + 1], apl, rh + 2);
            }
        }
        __syncthreads();
    }

    // Normalize and write ctx as bf16 hi/lo split (row-major [MROWS, DD])
    const float inv0 = 1.f / l0, inv1 = 1.f / l1;
    const size_t r0idx = ((size_t)b * SS + qbase + wm + g) * DD + h * DP;
    const size_t r1idx = r0idx + 8 * DD;
#pragma unroll
    for (int nj = 0; nj < 10; nj++) {
        const int col = nj * 8 + t4 * 2;
        uint32_t h0, l0p, h1, l1p;
        split_pack2(oacc[nj][0] * inv0, oacc[nj][1] * inv0, h0, l0p);
        split_pack2(oacc[nj][2] * inv1, oacc[nj][3] * inv1, h1, l1p);
        *(uint32_t*)&g_Chi[r0idx + col] = h0;
        *(uint32_t*)&g_Clo[r0idx + col] = l0p;
        *(uint32_t*)&g_Chi[r1idx + col] = h1;
        *(uint32_t*)&g_Clo[r1idx + col] = l1p;
    }
}

// ---------------------------------------------------------------------------
extern "C" void kernel_launch(void* const* d_in, const int* in_sizes, int n_in,
                              void* d_out, int out_size)
{
    const float* x  = (const float*)d_in[0];
    const float* Wq = (const float*)d_in[2];
    const float* bq = (const float*)d_in[3];
    const float* Wk = (const float*)d_in[4];
    const float* bk = (const float*)d_in[5];
    const float* Wv = (const float*)d_in[6];
    const float* bv = (const float*)d_in[7];
    const float* Wo = (const float*)d_in[8];
    const float* bo = (const float*)d_in[9];
    float* out = (float*)d_out;

    __nv_bfloat16 *xhi, *xlo, *wthi, *wtlo, *chi, *clo;
    cudaGetSymbolAddress((void**)&xhi, g_Xhi);
    cudaGetSymbolAddress((void**)&xlo, g_Xlo);
    cudaGetSymbolAddress((void**)&wthi, g_WThi);
    cudaGetSymbolAddress((void**)&wtlo, g_WTlo);
    cudaGetSymbolAddress((void**)&chi, g_Chi);
    cudaGetSymbolAddress((void**)&clo, g_Clo);

    // 1. split x
    {
        const int n2 = MROWS * DD / 2;
        split_kernel<<<(n2 + 255) / 256, 256>>>(x, xhi, xlo, n2);
    }
    // 2. transpose+split weights (one launch, z selects matrix)
    wsplit4_kernel<<<dim3(40, 40, 4), dim3(32, 8)>>>(Wq, Wk, Wv, Wo);

    // 3. QKV projection (256x128 tiles)
    cudaFuncSetAttribute(mma_gemm_kernel, cudaFuncAttributeMaxDynamicSharedMemorySize, GEMM_SMEM_BYTES);
    mma_gemm_kernel<<<dim3(NQKV / 128, MROWS / 256), 512, GEMM_SMEM_BYTES>>>(
        xhi, xlo, wthi, wtlo, bq, bk, bv, 0, nullptr);

    // 4. attention (HMMA flash, double-buffered K/V pipeline)
    cudaFuncSetAttribute(attn_mma_kernel, cudaFuncAttributeMaxDynamicSharedMemorySize, ATT_SMEM_BYTES);
    attn_mma_kernel<<<256, 512, ATT_SMEM_BYTES>>>();

    // 5. output projection (256x128 tiles)
    mma_gemm_kernel<<<dim3(DD / 128, MROWS / 256), 512, GEMM_SMEM_BYTES>>>(
        chi, clo, wthi + (size_t)3 * DD * DD, wtlo + (size_t)3 * DD * DD,
        bo, nullptr, nullptr, 1, out);
}

// round 12
// speedup vs baseline: 1.0714x; 1.0714x over previous
#include <cuda_runtime.h>
#include <cuda_bf16.h>
#include <cstdint>
#include <math.h>

// Problem constants
#define BB 2
#define SS 2048
#define DD 1280
#define HH 16
#define DP 80
#define MROWS (BB * SS)          // 4096
#define NQKV (3 * DD)            // 3840

// ---------------------------------------------------------------------------
// Device scratch (allocation-free rule)
// ---------------------------------------------------------------------------
__device__ __nv_bfloat16 g_Qhi[BB * HH * SS * DP];
__device__ __nv_bfloat16 g_Qlo[BB * HH * SS * DP];
__device__ __nv_bfloat16 g_Khi[BB * HH * SS * DP];
__device__ __nv_bfloat16 g_Klo[BB * HH * SS * DP];
__device__ __nv_bfloat16 g_Vhi[BB * HH * SS * DP];
__device__ __nv_bfloat16 g_Vlo[BB * HH * SS * DP];

__device__ __nv_bfloat16 g_Xhi[MROWS * DD];
__device__ __nv_bfloat16 g_Xlo[MROWS * DD];
__device__ __nv_bfloat16 g_WThi[4 * DD * DD];   // rows [0,3840)=Wq,Wk,Wv^T ; [3840,5120)=Wo^T
__device__ __nv_bfloat16 g_WTlo[4 * DD * DD];
__device__ __nv_bfloat16 g_Chi[MROWS * DD];
__device__ __nv_bfloat16 g_Clo[MROWS * DD];

// ---------------------------------------------------------------------------
// mma.sync + ldmatrix + cp.async helpers (portable to sm_103)
// ---------------------------------------------------------------------------
__device__ __forceinline__ void mma16816(float* c, const uint32_t* a, const uint32_t* b) {
    asm volatile(
        "mma.sync.aligned.m16n8k16.row.col.f32.bf16.bf16.f32 "
        "{%0,%1,%2,%3}, {%4,%5,%6,%7}, {%8,%9}, {%0,%1,%2,%3};"
        : "+f"(c[0]), "+f"(c[1]), "+f"(c[2]), "+f"(c[3])
        : "r"(a[0]), "r"(a[1]), "r"(a[2]), "r"(a[3]), "r"(b[0]), "r"(b[1]));
}

__device__ __forceinline__ void ldsm_x4(uint32_t* r, uint32_t addr) {
    asm volatile("ldmatrix.sync.aligned.m8n8.x4.shared.b16 {%0,%1,%2,%3}, [%4];"
        : "=r"(r[0]), "=r"(r[1]), "=r"(r[2]), "=r"(r[3]) : "r"(addr));
}
__device__ __forceinline__ void ldsm_x4_t(uint32_t* r, uint32_t addr) {
    asm volatile("ldmatrix.sync.aligned.m8n8.x4.trans.shared.b16 {%0,%1,%2,%3}, [%4];"
        : "=r"(r[0]), "=r"(r[1]), "=r"(r[2]), "=r"(r[3]) : "r"(addr));
}

__device__ __forceinline__ uint32_t smem_u32(const void* p) {
    return (uint32_t)__cvta_generic_to_shared(p);
}

__device__ __forceinline__ void cp_async16(uint32_t dst, const void* src) {
    asm volatile("cp.async.ca.shared.global [%0], [%1], 16;" :: "r"(dst), "l"(src));
}
__device__ __forceinline__ void cp_commit() {
    asm volatile("cp.async.commit_group;");
}

// split a,b -> packed bf16x2 hi and lo
__device__ __forceinline__ void split_pack2(float a, float b, uint32_t& hi, uint32_t& lo) {
    __nv_bfloat16 ha = __float2bfloat16(a), hb = __float2bfloat16(b);
    __nv_bfloat16 la = __float2bfloat16(a - __bfloat162float(ha));
    __nv_bfloat16 lb = __float2bfloat16(b - __bfloat162float(hb));
    __nv_bfloat162 H = __nv_bfloat162(ha, hb);
    __nv_bfloat162 L = __nv_bfloat162(la, lb);
    hi = *(uint32_t*)&H;
    lo = *(uint32_t*)&L;
}

// ---------------------------------------------------------------------------
// fp32 -> (bf16 hi, bf16 lo) elementwise split
// ---------------------------------------------------------------------------
__global__ __launch_bounds__(256) void split_kernel(const float* __restrict__ src,
                                                    __nv_bfloat16* __restrict__ hi,
                                                    __nv_bfloat16* __restrict__ lo,
                                                    int n2) {
    int i = blockIdx.x * blockDim.x + threadIdx.x;
    if (i >= n2) return;
    float2 v = *(const float2*)(src + 2 * (size_t)i);
    __nv_bfloat16 h0 = __float2bfloat16(v.x);
    __nv_bfloat16 h1 = __float2bfloat16(v.y);
    __nv_bfloat16 l0 = __float2bfloat16(v.x - __bfloat162float(h0));
    __nv_bfloat16 l1 = __float2bfloat16(v.y - __bfloat162float(h1));
    *(__nv_bfloat162*)(hi + 2 * (size_t)i) = __nv_bfloat162(h0, h1);
    *(__nv_bfloat162*)(lo + 2 * (size_t)i) = __nv_bfloat162(l0, l1);
}

// ---------------------------------------------------------------------------
// W [K=1280, N=1280] row-major -> W^T split; blockIdx.z selects matrix
// ---------------------------------------------------------------------------
__global__ __launch_bounds__(256) void wsplit4_kernel(const float* __restrict__ W0,
                                                      const float* __restrict__ W1,
                                                      const float* __restrict__ W2,
                                                      const float* __restrict__ W3) {
    __shared__ float tile[32][33];
    const int z  = blockIdx.z;
    const float* W = (z == 0) ? W0 : (z == 1) ? W1 : (z == 2) ? W2 : W3;
    const int ro = z * DD;
    const int tx = threadIdx.x;
    const int ty = threadIdx.y;
    const int n0 = blockIdx.x * 32;
    const int k0 = blockIdx.y * 32;
#pragma unroll
    for (int q = 0; q < 4; q++)
        tile[ty + q * 8][tx] = W[(size_t)(k0 + ty + q * 8) * DD + n0 + tx];
    __syncthreads();
#pragma unroll
    for (int q = 0; q < 4; q++) {
        const int nn = n0 + ty + q * 8;
        const int kk = k0 + tx;
        float v = tile[tx][ty + q * 8];
        __nv_bfloat16 h = __float2bfloat16(v);
        __nv_bfloat16 l = __float2bfloat16(v - __bfloat162float(h));
        g_WThi[(size_t)(ro + nn) * DD + kk] = h;
        g_WTlo[(size_t)(ro + nn) * DD + kk] = l;
    }
}

// ---------------------------------------------------------------------------
// HMMA split-bf16 GEMM (R9 shape): 128x128 tile, 256 threads, 2 CTAs/SM,
// 2-stage cp.async, ldmatrix feeds. MMA issue reordered: products outermost
// so consecutive MMAs hit different accumulators (dep distance 1 -> 4).
// ---------------------------------------------------------------------------
#define BK2 32
#define AP 40                       // smem pitch in bf16 (80B rows)
#define GSTR (128 * AP)             // bf16 per array per stage
#define GEMM_SMEM_BYTES (2 * 4 * GSTR * 2)   // 2 stages x 4 arrays

__global__ __launch_bounds__(256, 2) void mma_gemm_kernel(
    const __nv_bfloat16* __restrict__ Ahi, const __nv_bfloat16* __restrict__ Alo,
    const __nv_bfloat16* __restrict__ Bhi, const __nv_bfloat16* __restrict__ Blo,
    const float* __restrict__ b0, const float* __restrict__ b1, const float* __restrict__ b2,
    int mode, float* __restrict__ outp)
{
    extern __shared__ __nv_bfloat16 dsm[];

    const int t    = threadIdx.x;
    const int wid  = t >> 5;
    const int lane = t & 31;
    const int n0   = blockIdx.x * 128;
    const int m0   = blockIdx.y * 128;
    const int wm   = (wid >> 2) * 64;
    const int wn   = (wid & 3) * 32;
    const int g    = lane >> 2;
    const int t4   = lane & 3;

    const int a_r = (lane & 7) + ((lane >> 3) & 1) * 8;
    const int a_c = (lane >> 4) * 8;
    const int b_r = (lane & 7) + ((lane >> 4) & 1) * 8;
    const int b_c = ((lane >> 3) & 1) * 8;

    const uint32_t sbase = smem_u32(dsm);

    const int lr = t >> 1;
    const int lc = (t & 1) * 16;

    const __nv_bfloat16* rowA_hi = Ahi + (size_t)(m0 + lr) * DD + lc;
    const __nv_bfloat16* rowA_lo = Alo + (size_t)(m0 + lr) * DD + lc;
    const __nv_bfloat16* rowB_hi = Bhi + (size_t)(n0 + lr) * DD + lc;
    const __nv_bfloat16* rowB_lo = Blo + (size_t)(n0 + lr) * DD + lc;
    const uint32_t dst_off = (uint32_t)((lr * AP + lc) * 2);

    float acc[4][4][4];
#pragma unroll
    for (int mi = 0; mi < 4; mi++)
#pragma unroll
        for (int ni = 0; ni < 4; ni++)
#pragma unroll
            for (int q = 0; q < 4; q++) acc[mi][ni][q] = 0.f;

    const int KCH = DD / BK2;       // 40

    {
        const uint32_t sb = sbase + dst_off;
        cp_async16(sb + 0 * GSTR * 2,      rowA_hi);
        cp_async16(sb + 0 * GSTR * 2 + 16, rowA_hi + 8);
        cp_async16(sb + 1 * GSTR * 2,      rowA_lo);
        cp_async16(sb + 1 * GSTR * 2 + 16, rowA_lo + 8);
        cp_async16(sb + 2 * GSTR * 2,      rowB_hi);
        cp_async16(sb + 2 * GSTR * 2 + 16, rowB_hi + 8);
        cp_async16(sb + 3 * GSTR * 2,      rowB_lo);
        cp_async16(sb + 3 * GSTR * 2 + 16, rowB_lo + 8);
        cp_commit();
    }

    for (int kc = 0; kc < KCH; kc++) {
        if (kc + 1 < KCH) {
            const int kk = (kc + 1) * BK2;
            const uint32_t sb = sbase + (uint32_t)(((kc + 1) & 1) * 4 * GSTR * 2) + dst_off;
            cp_async16(sb + 0 * GSTR * 2,      rowA_hi + kk);
            cp_async16(sb + 0 * GSTR * 2 + 16, rowA_hi + kk + 8);
            cp_async16(sb + 1 * GSTR * 2,      rowA_lo + kk);
            cp_async16(sb + 1 * GSTR * 2 + 16, rowA_lo + kk + 8);
            cp_async16(sb + 2 * GSTR * 2,      rowB_hi + kk);
            cp_async16(sb + 2 * GSTR * 2 + 16, rowB_hi + kk + 8);
            cp_async16(sb + 3 * GSTR * 2,      rowB_lo + kk);
            cp_async16(sb + 3 * GSTR * 2 + 16, rowB_lo + kk + 8);
            cp_commit();
            asm volatile("cp.async.wait_group 1;");
        } else {
            asm volatile("cp.async.wait_group 0;");
        }
        __syncthreads();

        const uint32_t st = sbase + (uint32_t)((kc & 1) * 4 * GSTR * 2);
        const uint32_t uAhi = st;
        const uint32_t uAlo = st + 1 * GSTR * 2;
        const uint32_t uBhi = st + 2 * GSTR * 2;
        const uint32_t uBlo = st + 3 * GSTR * 2;

#pragma unroll
        for (int ks = 0; ks < 2; ks++) {
            const int kb = ks * 16;
            uint32_t bh[4][2], bl[4][2];
#pragma unroll
            for (int p = 0; p < 2; p++) {
                const uint32_t off = (uint32_t)(((wn + p * 16 + b_r) * AP + kb + b_c) * 2);
                uint32_t r4[4];
                ldsm_x4(r4, uBhi + off);
                bh[2 * p][0] = r4[0]; bh[2 * p][1] = r4[1];
                bh[2 * p + 1][0] = r4[2]; bh[2 * p + 1][1] = r4[3];
                ldsm_x4(r4, uBlo + off);
                bl[2 * p][0] = r4[0]; bl[2 * p][1] = r4[1];
                bl[2 * p + 1][0] = r4[2]; bl[2 * p + 1][1] = r4[3];
            }
#pragma unroll
            for (int mi = 0; mi < 4; mi++) {
                const uint32_t off = (uint32_t)(((wm + mi * 16 + a_r) * AP + kb + a_c) * 2);
                uint32_t ah[4], al[4];
                ldsm_x4(ah, uAhi + off);
                ldsm_x4(al, uAlo + off);
                // products outermost: consecutive MMAs use different accumulators
#pragma unroll
                for (int ni = 0; ni < 4; ni++) mma16816(acc[mi][ni], ah, bh[ni]);
#pragma unroll
                for (int ni = 0; ni < 4; ni++) mma16816(acc[mi][ni], ah, bl[ni]);
#pragma unroll
                for (int ni = 0; ni < 4; ni++) mma16816(acc[mi][ni], al, bh[ni]);
            }
        }
        __syncthreads();
    }

    // Epilogue (R9 direct scatter)
#pragma unroll
    for (int mi = 0; mi < 4; mi++) {
        const int r0 = m0 + wm + mi * 16 + g;
#pragma unroll
        for (int ni = 0; ni < 4; ni++) {
            const int cg0 = n0 + wn + ni * 8 + t4 * 2;
#pragma unroll
            for (int q = 0; q < 4; q++) {
                const int row = r0 + (q >> 1) * 8;
                const int cg  = cg0 + (q & 1);
                const float v = acc[mi][ni][q];
                if (mode == 0) {
                    const int which = cg / DD;
                    const int cl    = cg - which * DD;
                    const int head  = cl / DP;
                    const int dd    = cl - head * DP;
                    const float val = v + (which == 0 ? b0 : which == 1 ? b1 : b2)[cl];
                    __nv_bfloat16* dh = (which == 0) ? g_Qhi : (which == 1) ? g_Khi : g_Vhi;
                    __nv_bfloat16* dl = (which == 0) ? g_Qlo : (which == 1) ? g_Klo : g_Vlo;
                    const int b_ = row >> 11;
                    const int s_ = row & 2047;
                    const size_t idx = (((size_t)b_ * HH + head) * SS + s_) * DP + dd;
                    __nv_bfloat16 hv = __float2bfloat16(val);
                    dh[idx] = hv;
                    dl[idx] = __float2bfloat16(val - __bfloat162float(hv));
                } else {
                    outp[(size_t)row * DD + cg] = v + b0[cg];
                }
            }
        }
    }
}

// ---------------------------------------------------------------------------
// HMMA flash attention: 256 q-rows/CTA, 512 threads (16 warps x 16 rows),
// 64-key tiles, 2-stage cp.async K/V pipeline. MMA issue interleaved across
// even/odd n-fragments (accumulator dep distance 1 -> 2).
// ---------------------------------------------------------------------------
#define QP 88                       // smem pitch bf16 (176B rows)
#define QROWS 256
#define KVSTG (4 * 64 * QP)         // bf16 per K/V stage (Kh,Kl,Vh,Vl)
#define ATT_SMEM_BYTES ((2 * QROWS * QP + 2 * KVSTG) * 2)

__global__ __launch_bounds__(512, 1) void attn_mma_kernel()
{
    extern __shared__ __nv_bfloat16 sm[];
    __nv_bfloat16* sQh = sm;
    __nv_bfloat16* sQl = sm + QROWS * QP;

    const int t    = threadIdx.x;
    const int wid  = t >> 5;
    const int lane = t & 31;
    const int g    = lane >> 2;
    const int t4   = lane & 3;
    const int idx   = blockIdx.x;            // 0..255
    const int qt    = 7 - (idx >> 5);        // 8 q-tiles, big first
    const int hb    = idx & 31;
    const int h     = hb & 15;
    const int b     = hb >> 4;
    const size_t bh_off = ((size_t)b * HH + h) * SS * DP;
    const int qbase = qt * QROWS;
    const int wm    = wid * 16;
    const float scale = 0.11180339887498948f;   // 1/sqrt(80)

    const int a_r = (lane & 7) + ((lane >> 3) & 1) * 8;
    const int a_c = (lane >> 4) * 8;
    const int b_r = (lane & 7) + ((lane >> 4) & 1) * 8;
    const int b_c = ((lane >> 3) & 1) * 8;
    const int v_r = (lane & 7) + ((lane >> 3) & 1) * 8;
    const int v_c = ((lane >> 4) & 1) * 8;

    const uint32_t uQh = smem_u32(sQh), uQl = smem_u32(sQl);
    const uint32_t uKV = smem_u32(sm + 2 * QROWS * QP);

    const int ktiles = 4 * qt + 4;

    // Prologue: Q tile (256x80 hi+lo) + K/V tile 0, one cp.async group
    {
        const size_t qbyte = (bh_off + (size_t)qbase * DP) * 2;
        const char* qh = (const char*)g_Qhi + qbyte;
        const char* ql = (const char*)g_Qlo + qbyte;
#pragma unroll
        for (int it = 0; it < 10; it++) {
            const int id2 = t + it * 512;
            const int arr = id2 / 2560;
            const int rem = id2 - arr * 2560;
            const int row = rem / 10;
            const int c16 = rem - row * 10;
            cp_async16((arr ? uQl : uQh) + (uint32_t)(row * (QP * 2) + c16 * 16),
                       (arr ? ql : qh) + (size_t)row * (DP * 2) + c16 * 16);
        }
        const size_t kbyte = bh_off * 2;
        const char* srcs[4] = {
            (const char*)g_Khi + kbyte, (const char*)g_Klo + kbyte,
            (const char*)g_Vhi + kbyte, (const char*)g_Vlo + kbyte };
#pragma unroll
        for (int it = 0; it < 5; it++) {
            const int id2 = t + it * 512;
            const int arr = id2 / 640;
            const int rem = id2 - arr * 640;
            const int row = rem / 10;
            const int c16 = rem - row * 10;
            cp_async16(uKV + (uint32_t)(arr * (64 * QP * 2) + row * (QP * 2) + c16 * 16),
                       srcs[arr] + (size_t)row * (DP * 2) + c16 * 16);
        }
        cp_commit();
    }

    float oacc[10][4];
#pragma unroll
    for (int nj = 0; nj < 10; nj++)
#pragma unroll
        for (int q = 0; q < 4; q++) oacc[nj][q] = 0.f;
    float m0 = -1e30f, m1 = -1e30f, l0 = 0.f, l1 = 0.f;

    const int gr0 = qbase + wm + g;
    const int gr1 = gr0 + 8;

    for (int kb = 0; kb < ktiles; kb++) {
        if (kb + 1 < ktiles) {
            const size_t kbyte = (bh_off + (size_t)(kb + 1) * 64 * DP) * 2;
            const char* srcs[4] = {
                (const char*)g_Khi + kbyte, (const char*)g_Klo + kbyte,
                (const char*)g_Vhi + kbyte, (const char*)g_Vlo + kbyte };
            const uint32_t dstb = uKV + (uint32_t)(((kb + 1) & 1) * KVSTG * 2);
#pragma unroll
            for (int it = 0; it < 5; it++) {
                const int id2 = t + it * 512;
                const int arr = id2 / 640;
                const int rem = id2 - arr * 640;
                const int row = rem / 10;
                const int c16 = rem - row * 10;
                cp_async16(dstb + (uint32_t)(arr * (64 * QP * 2) + row * (QP * 2) + c16 * 16),
                           srcs[arr] + (size_t)row * (DP * 2) + c16 * 16);
            }
            cp_commit();
            asm volatile("cp.async.wait_group 1;");
        } else {
            asm volatile("cp.async.wait_group 0;");
        }
        __syncthreads();

        const uint32_t stb = uKV + (uint32_t)((kb & 1) * KVSTG * 2);
        const uint32_t uKh = stb;
        const uint32_t uKl = stb + (uint32_t)(64 * QP * 2);
        const uint32_t uVh = stb + (uint32_t)(2 * 64 * QP * 2);
        const uint32_t uVl = stb + (uint32_t)(3 * 64 * QP * 2);

        // S = Q @ K^T (interleaved issue: dep distance 2)
        float sacc[8][4];
#pragma unroll
        for (int ni = 0; ni < 8; ni++)
#pragma unroll
            for (int q = 0; q < 4; q++) sacc[ni][q] = 0.f;

#pragma unroll
        for (int kc = 0; kc < 5; kc++) {
            const int ko = kc * 16;
            uint32_t ah[4], al[4];
            ldsm_x4(ah, uQh + (uint32_t)(((wm + a_r) * QP + ko + a_c) * 2));
            ldsm_x4(al, uQl + (uint32_t)(((wm + a_r) * QP + ko + a_c) * 2));
#pragma unroll
            for (int p = 0; p < 4; p++) {
                const uint32_t off = (uint32_t)(((p * 16 + b_r) * QP + ko + b_c) * 2);
                uint32_t rh[4], rl[4];
                ldsm_x4(rh, uKh + off);
                ldsm_x4(rl, uKl + off);
                mma16816(sacc[2 * p],     ah, rh);
                mma16816(sacc[2 * p + 1], ah, rh + 2);
                mma16816(sacc[2 * p],     ah, rl);
                mma16816(sacc[2 * p + 1], ah, rl + 2);
                mma16816(sacc[2 * p],     al, rh);
                mma16816(sacc[2 * p + 1], al, rh + 2);
            }
        }

        // scale + causal mask (additive -10000, matches reference)
        const bool edge = (kb >= 4 * qt);
#pragma unroll
        for (int ni = 0; ni < 8; ni++) {
#pragma unroll
            for (int q = 0; q < 4; q++) {
                float v = sacc[ni][q] * scale;
                if (edge) {
                    const int key = kb * 64 + ni * 8 + t4 * 2 + (q & 1);
                    const int qr  = (q < 2) ? gr0 : gr1;
                    if (key > qr) v -= 10000.f;
                }
                sacc[ni][q] = v;
            }
        }

        // online softmax
        float mx0 = -1e30f, mx1 = -1e30f;
#pragma unroll
        for (int ni = 0; ni < 8; ni++) {
            mx0 = fmaxf(mx0, fmaxf(sacc[ni][0], sacc[ni][1]));
            mx1 = fmaxf(mx1, fmaxf(sacc[ni][2], sacc[ni][3]));
        }
        mx0 = fmaxf(mx0, __shfl_xor_sync(0xffffffffu, mx0, 1));
        mx0 = fmaxf(mx0, __shfl_xor_sync(0xffffffffu, mx0, 2));
        mx1 = fmaxf(mx1, __shfl_xor_sync(0xffffffffu, mx1, 1));
        mx1 = fmaxf(mx1, __shfl_xor_sync(0xffffffffu, mx1, 2));
        const float mn0 = fmaxf(m0, mx0), mn1 = fmaxf(m1, mx1);
        const float c0 = __expf(m0 - mn0), c1 = __expf(m1 - mn1);
        float s0 = 0.f, s1 = 0.f;
#pragma unroll
        for (int ni = 0; ni < 8; ni++) {
            sacc[ni][0] = __expf(sacc[ni][0] - mn0);
            sacc[ni][1] = __expf(sacc[ni][1] - mn0);
            sacc[ni][2] = __expf(sacc[ni][2] - mn1);
            sacc[ni][3] = __expf(sacc[ni][3] - mn1);
            s0 += sacc[ni][0] + sacc[ni][1];
            s1 += sacc[ni][2] + sacc[ni][3];
        }
        s0 += __shfl_xor_sync(0xffffffffu, s0, 1);
        s0 += __shfl_xor_sync(0xffffffffu, s0, 2);
        s1 += __shfl_xor_sync(0xffffffffu, s1, 1);
        s1 += __shfl_xor_sync(0xffffffffu, s1, 2);
        l0 = l0 * c0 + s0;  m0 = mn0;
        l1 = l1 * c1 + s1;  m1 = mn1;

#pragma unroll
        for (int nj = 0; nj < 10; nj++) {
            oacc[nj][0] *= c0; oacc[nj][1] *= c0;
            oacc[nj][2] *= c1; oacc[nj][3] *= c1;
        }

        // O += P @ V (interleaved issue: dep distance 2)
#pragma unroll
        for (int kc2 = 0; kc2 < 4; kc2++) {
            uint32_t aph[4], apl[4];
            split_pack2(sacc[2 * kc2][0],     sacc[2 * kc2][1],     aph[0], apl[0]);
            split_pack2(sacc[2 * kc2][2],     sacc[2 * kc2][3],     aph[1], apl[1]);
            split_pack2(sacc[2 * kc2 + 1][0], sacc[2 * kc2 + 1][1], aph[2], apl[2]);
            split_pack2(sacc[2 * kc2 + 1][2], sacc[2 * kc2 + 1][3], aph[3], apl[3]);
            const int ko2 = kc2 * 16;
#pragma unroll
            for (int p = 0; p < 5; p++) {
                const uint32_t off = (uint32_t)(((ko2 + v_r) * QP + p * 16 + v_c) * 2);
                uint32_t rh[4], rl[4];
                ldsm_x4_t(rh, uVh + off);
                ldsm_x4_t(rl, uVl + off);
                mma16816(oacc[2 * p],     aph, rh);
                mma16816(oacc[2 * p + 1], aph, rh + 2);
                mma16816(oacc[2 * p],     aph, rl);
                mma16816(oacc[2 * p + 1], aph, rl + 2);
                mma16816(oacc[2 * p],     apl, rh);
                mma16816(oacc[2 * p + 1], apl, rh + 2);
            }
        }
        __syncthreads();
    }

    // Normalize and write ctx as bf16 hi/lo split (row-major [MROWS, DD])
    const float inv0 = 1.f / l0, inv1 = 1.f / l1;
    const size_t r0idx = ((size_t)b * SS + qbase + wm + g) * DD + h * DP;
    const size_t r1idx = r0idx + 8 * DD;
#pragma unroll
    for (int nj = 0; nj < 10; nj++) {
        const int col = nj * 8 + t4 * 2;
        uint32_t h0, l0p, h1, l1p;
        split_pack2(oacc[nj][0] * inv0, oacc[nj][1] * inv0, h0, l0p);
        split_pack2(oacc[nj][2] * inv1, oacc[nj][3] * inv1, h1, l1p);
        *(uint32_t*)&g_Chi[r0idx + col] = h0;
        *(uint32_t*)&g_Clo[r0idx + col] = l0p;
        *(uint32_t*)&g_Chi[r1idx + col] = h1;
        *(uint32_t*)&g_Clo[r1idx + col] = l1p;
    }
}

// ---------------------------------------------------------------------------
extern "C" void kernel_launch(void* const* d_in, const int* in_sizes, int n_in,
                              void* d_out, int out_size)
{
    const float* x  = (const float*)d_in[0];
    const float* Wq = (const float*)d_in[2];
    const float* bq = (const float*)d_in[3];
    const float* Wk = (const float*)d_in[4];
    const float* bk = (const float*)d_in[5];
    const float* Wv = (const float*)d_in[6];
    const float* bv = (const float*)d_in[7];
    const float* Wo = (const float*)d_in[8];
    const float* bo = (const float*)d_in[9];
    float* out = (float*)d_out;

    __nv_bfloat16 *xhi, *xlo, *wthi, *wtlo, *chi, *clo;
    cudaGetSymbolAddress((void**)&xhi, g_Xhi);
    cudaGetSymbolAddress((void**)&xlo, g_Xlo);
    cudaGetSymbolAddress((void**)&wthi, g_WThi);
    cudaGetSymbolAddress((void**)&wtlo, g_WTlo);
    cudaGetSymbolAddress((void**)&chi, g_Chi);
    cudaGetSymbolAddress((void**)&clo, g_Clo);

    // 1. split x
    {
        const int n2 = MROWS * DD / 2;
        split_kernel<<<(n2 + 255) / 256, 256>>>(x, xhi, xlo, n2);
    }
    // 2. transpose+split weights (one launch, z selects matrix)
    wsplit4_kernel<<<dim3(40, 40, 4), dim3(32, 8)>>>(Wq, Wk, Wv, Wo);

    // 3. QKV projection (128x128 tiles, reordered MMA issue)
    cudaFuncSetAttribute(mma_gemm_kernel, cudaFuncAttributeMaxDynamicSharedMemorySize, GEMM_SMEM_BYTES);
    mma_gemm_kernel<<<dim3(NQKV / 128, MROWS / 128), 256, GEMM_SMEM_BYTES>>>(
        xhi, xlo, wthi, wtlo, bq, bk, bv, 0, nullptr);

    // 4. attention (HMMA flash, double-buffered K/V pipeline, reordered MMA)
    cudaFuncSetAttribute(attn_mma_kernel, cudaFuncAttributeMaxDynamicSharedMemorySize, ATT_SMEM_BYTES);
    attn_mma_kernel<<<256, 512, ATT_SMEM_BYTES>>>();

    // 5. output projection (128x128 tiles, reordered MMA issue)
    mma_gemm_kernel<<<dim3(DD / 128, MROWS / 128), 256, GEMM_SMEM_BYTES>>>(
        chi, clo, wthi + (size_t)3 * DD * DD, wtlo + (size_t)3 * DD * DD,
        bo, nullptr, nullptr, 1, out);
}

// round 14
// speedup vs baseline: 1.0904x; 1.0177x over previous
#include <cuda_runtime.h>
#include <cuda_bf16.h>
#include <cstdint>
#include <math.h>

// Problem constants
#define BB 2
#define SS 2048
#define DD 1280
#define HH 16
#define DP 80
#define MROWS (BB * SS)          // 4096
#define NQKV (3 * DD)            // 3840

// ---------------------------------------------------------------------------
// Device scratch (allocation-free rule)
// ---------------------------------------------------------------------------
__device__ __nv_bfloat16 g_Qhi[BB * HH * SS * DP];
__device__ __nv_bfloat16 g_Qlo[BB * HH * SS * DP];
__device__ __nv_bfloat16 g_Khi[BB * HH * SS * DP];
__device__ __nv_bfloat16 g_Klo[BB * HH * SS * DP];
__device__ __nv_bfloat16 g_Vhi[BB * HH * SS * DP];
__device__ __nv_bfloat16 g_Vlo[BB * HH * SS * DP];

__device__ __nv_bfloat16 g_Xhi[MROWS * DD];
__device__ __nv_bfloat16 g_Xlo[MROWS * DD];
__device__ __nv_bfloat16 g_WThi[4 * DD * DD];   // rows [0,3840)=Wq,Wk,Wv^T ; [3840,5120)=Wo^T
__device__ __nv_bfloat16 g_WTlo[4 * DD * DD];
__device__ __nv_bfloat16 g_Chi[MROWS * DD];
__device__ __nv_bfloat16 g_Clo[MROWS * DD];

// ---------------------------------------------------------------------------
// mma.sync + ldmatrix + cp.async helpers (portable to sm_103)
// ---------------------------------------------------------------------------
__device__ __forceinline__ void mma16816(float* c, const uint32_t* a, const uint32_t* b) {
    asm volatile(
        "mma.sync.aligned.m16n8k16.row.col.f32.bf16.bf16.f32 "
        "{%0,%1,%2,%3}, {%4,%5,%6,%7}, {%8,%9}, {%0,%1,%2,%3};"
        : "+f"(c[0]), "+f"(c[1]), "+f"(c[2]), "+f"(c[3])
        : "r"(a[0]), "r"(a[1]), "r"(a[2]), "r"(a[3]), "r"(b[0]), "r"(b[1]));
}

__device__ __forceinline__ void ldsm_x4(uint32_t* r, uint32_t addr) {
    asm volatile("ldmatrix.sync.aligned.m8n8.x4.shared.b16 {%0,%1,%2,%3}, [%4];"
        : "=r"(r[0]), "=r"(r[1]), "=r"(r[2]), "=r"(r[3]) : "r"(addr));
}
__device__ __forceinline__ void ldsm_x4_t(uint32_t* r, uint32_t addr) {
    asm volatile("ldmatrix.sync.aligned.m8n8.x4.trans.shared.b16 {%0,%1,%2,%3}, [%4];"
        : "=r"(r[0]), "=r"(r[1]), "=r"(r[2]), "=r"(r[3]) : "r"(addr));
}

__device__ __forceinline__ uint32_t smem_u32(const void* p) {
    return (uint32_t)__cvta_generic_to_shared(p);
}

__device__ __forceinline__ void cp_async16(uint32_t dst, const void* src) {
    asm volatile("cp.async.ca.shared.global [%0], [%1], 16;" :: "r"(dst), "l"(src));
}
__device__ __forceinline__ void cp_commit() {
    asm volatile("cp.async.commit_group;");
}

// split a,b -> packed bf16x2 hi and lo
__device__ __forceinline__ void split_pack2(float a, float b, uint32_t& hi, uint32_t& lo) {
    __nv_bfloat16 ha = __float2bfloat16(a), hb = __float2bfloat16(b);
    __nv_bfloat16 la = __float2bfloat16(a - __bfloat162float(ha));
    __nv_bfloat16 lb = __float2bfloat16(b - __bfloat162float(hb));
    __nv_bfloat162 H = __nv_bfloat162(ha, hb);
    __nv_bfloat162 L = __nv_bfloat162(la, lb);
    hi = *(uint32_t*)&H;
    lo = *(uint32_t*)&L;
}

// ---------------------------------------------------------------------------
// fp32 -> (bf16 hi, bf16 lo) elementwise split
// ---------------------------------------------------------------------------
__global__ __launch_bounds__(256) void split_kernel(const float* __restrict__ src,
                                                    __nv_bfloat16* __restrict__ hi,
                                                    __nv_bfloat16* __restrict__ lo,
                                                    int n2) {
    int i = blockIdx.x * blockDim.x + threadIdx.x;
    if (i >= n2) return;
    float2 v = *(const float2*)(src + 2 * (size_t)i);
    __nv_bfloat16 h0 = __float2bfloat16(v.x);
    __nv_bfloat16 h1 = __float2bfloat16(v.y);
    __nv_bfloat16 l0 = __float2bfloat16(v.x - __bfloat162float(h0));
    __nv_bfloat16 l1 = __float2bfloat16(v.y - __bfloat162float(h1));
    *(__nv_bfloat162*)(hi + 2 * (size_t)i) = __nv_bfloat162(h0, h1);
    *(__nv_bfloat162*)(lo + 2 * (size_t)i) = __nv_bfloat162(l0, l1);
}

// ---------------------------------------------------------------------------
// W [K=1280, N=1280] row-major -> W^T split; blockIdx.z selects matrix
// ---------------------------------------------------------------------------
__global__ __launch_bounds__(256) void wsplit4_kernel(const float* __restrict__ W0,
                                                      const float* __restrict__ W1,
                                                      const float* __restrict__ W2,
                                                      const float* __restrict__ W3) {
    __shared__ float tile[32][33];
    const int z  = blockIdx.z;
    const float* W = (z == 0) ? W0 : (z == 1) ? W1 : (z == 2) ? W2 : W3;
    const int ro = z * DD;
    const int tx = threadIdx.x;
    const int ty = threadIdx.y;
    const int n0 = blockIdx.x * 32;
    const int k0 = blockIdx.y * 32;
#pragma unroll
    for (int q = 0; q < 4; q++)
        tile[ty + q * 8][tx] = W[(size_t)(k0 + ty + q * 8) * DD + n0 + tx];
    __syncthreads();
#pragma unroll
    for (int q = 0; q < 4; q++) {
        const int nn = n0 + ty + q * 8;
        const int kk = k0 + tx;
        float v = tile[tx][ty + q * 8];
        __nv_bfloat16 h = __float2bfloat16(v);
        __nv_bfloat16 l = __float2bfloat16(v - __bfloat162float(h));
        g_WThi[(size_t)(ro + nn) * DD + kk] = h;
        g_WTlo[(size_t)(ro + nn) * DD + kk] = l;
    }
}

// ---------------------------------------------------------------------------
// HMMA split-bf16 GEMM v3 (fixed loader): 128x64 CTA tile, 8 warps (4m x 2n)
// of 32x32, 256 threads, 3 CTAs/SM, 2-stage cp.async, ldmatrix feeds.
// Stage layout (rows x AP bf16): [0,128) Ahi | [128,256) Alo |
//                                [256,320) Bhi | [320,384) Blo
// ---------------------------------------------------------------------------
#define BK2 32
#define AP 40                         // smem pitch bf16 (80B rows)
#define STG384 (384 * AP)             // bf16 per stage
#define GEMM_SMEM_BYTES (2 * STG384 * 2)   // 61440 B

__global__ __launch_bounds__(256, 3) void mma_gemm_kernel(
    const __nv_bfloat16* __restrict__ Ahi, const __nv_bfloat16* __restrict__ Alo,
    const __nv_bfloat16* __restrict__ Bhi, const __nv_bfloat16* __restrict__ Blo,
    const float* __restrict__ b0, const float* __restrict__ b1, const float* __restrict__ b2,
    int mode, float* __restrict__ outp)
{
    extern __shared__ __nv_bfloat16 dsm[];

    const int t    = threadIdx.x;
    const int wid  = t >> 5;
    const int lane = t & 31;
    const int n0   = blockIdx.x * 64;
    const int m0   = blockIdx.y * 128;
    const int wm   = (wid >> 1) * 32;     // 0,32,64,96
    const int wn   = (wid & 1) * 32;      // 0,32
    const int g    = lane >> 2;
    const int t4   = lane & 3;

    const int a_r = (lane & 7) + ((lane >> 3) & 1) * 8;
    const int a_c = (lane >> 4) * 8;
    const int b_r = (lane & 7) + ((lane >> 4) & 1) * 8;
    const int b_c = ((lane >> 3) & 1) * 8;

    const uint32_t sbase = smem_u32(dsm);

    float acc[2][4][4];
#pragma unroll
    for (int mi = 0; mi < 2; mi++)
#pragma unroll
        for (int ni = 0; ni < 4; ni++)
#pragma unroll
            for (int q = 0; q < 4; q++) acc[mi][ni][q] = 0.f;

    const int KCH = DD / BK2;       // 40

    // loader: 384 rows x 4 x 16B = 1536 ops per chunk; row = idx>>2, c16 = idx&3
    // Reads exactly BK2=32 bf16 per row: src[kk + c16*8 .. kk + c16*8 + 8)
#define GEMM_LOAD_CHUNK(kk, sb)                                                \
    {                                                                          \
        _Pragma("unroll")                                                      \
        for (int it = 0; it < 6; it++) {                                       \
            const int idx = t + it * 256;                                      \
            if (idx < 1536) {                                                  \
                const int row = idx >> 2;                                      \
                const int c16 = idx & 3;                                       \
                const __nv_bfloat16* src;                                      \
                if (row < 128)      src = Ahi + (size_t)(m0 + row) * DD;       \
                else if (row < 256) src = Alo + (size_t)(m0 + row - 128) * DD; \
                else if (row < 320) src = Bhi + (size_t)(n0 + row - 256) * DD; \
                else                src = Blo + (size_t)(n0 + row - 320) * DD; \
                cp_async16((sb) + (uint32_t)(row * (AP * 2) + c16 * 16),       \
                           src + (kk) + c16 * 8);                              \
            }                                                                  \
        }                                                                      \
        cp_commit();                                                           \
    }

    GEMM_LOAD_CHUNK(0, sbase)

    for (int kc = 0; kc < KCH; kc++) {
        if (kc + 1 < KCH) {
            GEMM_LOAD_CHUNK((kc + 1) * BK2,
                            sbase + (uint32_t)(((kc + 1) & 1) * STG384 * 2))
            asm volatile("cp.async.wait_group 1;");
        } else {
            asm volatile("cp.async.wait_group 0;");
        }
        __syncthreads();

        const uint32_t st = sbase + (uint32_t)((kc & 1) * STG384 * 2);
        const uint32_t uAhi = st;
        const uint32_t uAlo = st + 128 * AP * 2;
        const uint32_t uBhi = st + 256 * AP * 2;
        const uint32_t uBlo = st + 320 * AP * 2;

#pragma unroll
        for (int ks = 0; ks < 2; ks++) {
            const int kb = ks * 16;
            uint32_t bh[4][2], bl[4][2];
#pragma unroll
            for (int p = 0; p < 2; p++) {
                const uint32_t off = (uint32_t)(((wn + p * 16 + b_r) * AP + kb + b_c) * 2);
                uint32_t r4[4];
                ldsm_x4(r4, uBhi + off);
                bh[2 * p][0] = r4[0]; bh[2 * p][1] = r4[1];
                bh[2 * p + 1][0] = r4[2]; bh[2 * p + 1][1] = r4[3];
                ldsm_x4(r4, uBlo + off);
                bl[2 * p][0] = r4[0]; bl[2 * p][1] = r4[1];
                bl[2 * p + 1][0] = r4[2]; bl[2 * p + 1][1] = r4[3];
            }
#pragma unroll
            for (int mi = 0; mi < 2; mi++) {
                const uint32_t off = (uint32_t)(((wm + mi * 16 + a_r) * AP + kb + a_c) * 2);
                uint32_t ah[4], al[4];
                ldsm_x4(ah, uAhi + off);
                ldsm_x4(al, uAlo + off);
#pragma unroll
                for (int ni = 0; ni < 4; ni++) mma16816(acc[mi][ni], ah, bh[ni]);
#pragma unroll
                for (int ni = 0; ni < 4; ni++) mma16816(acc[mi][ni], ah, bl[ni]);
#pragma unroll
                for (int ni = 0; ni < 4; ni++) mma16816(acc[mi][ni], al, bh[ni]);
            }
        }
        __syncthreads();
    }

    // Epilogue
#pragma unroll
    for (int mi = 0; mi < 2; mi++) {
        const int r0 = m0 + wm + mi * 16 + g;
#pragma unroll
        for (int ni = 0; ni < 4; ni++) {
            const int cg0 = n0 + wn + ni * 8 + t4 * 2;
#pragma unroll
            for (int q = 0; q < 4; q++) {
                const int row = r0 + (q >> 1) * 8;
                const int cg  = cg0 + (q & 1);
                const float v = acc[mi][ni][q];
                if (mode == 0) {
                    const int which = cg / DD;
                    const int cl    = cg - which * DD;
                    const int head  = cl / DP;
                    const int dd    = cl - head * DP;
                    const float val = v + (which == 0 ? b0 : which == 1 ? b1 : b2)[cl];
                    __nv_bfloat16* dh = (which == 0) ? g_Qhi : (which == 1) ? g_Khi : g_Vhi;
                    __nv_bfloat16* dl = (which == 0) ? g_Qlo : (which == 1) ? g_Klo : g_Vlo;
                    const int b_ = row >> 11;
                    const int s_ = row & 2047;
                    const size_t idx = (((size_t)b_ * HH + head) * SS + s_) * DP + dd;
                    __nv_bfloat16 hv = __float2bfloat16(val);
                    dh[idx] = hv;
                    dl[idx] = __float2bfloat16(val - __bfloat162float(hv));
                } else {
                    outp[(size_t)row * DD + cg] = v + b0[cg];
                }
            }
        }
    }
}

// ---------------------------------------------------------------------------
// HMMA flash attention (unchanged from best): 256 q-rows/CTA, 512 threads,
// 64-key tiles, 2-stage cp.async K/V pipeline.
// ---------------------------------------------------------------------------
#define QP 88                       // smem pitch bf16 (176B rows)
#define QROWS 256
#define KVSTG (4 * 64 * QP)         // bf16 per K/V stage (Kh,Kl,Vh,Vl)
#define ATT_SMEM_BYTES ((2 * QROWS * QP + 2 * KVSTG) * 2)

__global__ __launch_bounds__(512, 1) void attn_mma_kernel()
{
    extern __shared__ __nv_bfloat16 sm[];
    __nv_bfloat16* sQh = sm;
    __nv_bfloat16* sQl = sm + QROWS * QP;

    const int t    = threadIdx.x;
    const int wid  = t >> 5;
    const int lane = t & 31;
    const int g    = lane >> 2;
    const int t4   = lane & 3;
    const int idx   = blockIdx.x;            // 0..255
    const int qt    = 7 - (idx >> 5);        // 8 q-tiles, big first
    const int hb    = idx & 31;
    const int h     = hb & 15;
    const int b     = hb >> 4;
    const size_t bh_off = ((size_t)b * HH + h) * SS * DP;
    const int qbase = qt * QROWS;
    const int wm    = wid * 16;
    const float scale = 0.11180339887498948f;   // 1/sqrt(80)

    const int a_r = (lane & 7) + ((lane >> 3) & 1) * 8;
    const int a_c = (lane >> 4) * 8;
    const int b_r = (lane & 7) + ((lane >> 4) & 1) * 8;
    const int b_c = ((lane >> 3) & 1) * 8;
    const int v_r = (lane & 7) + ((lane >> 3) & 1) * 8;
    const int v_c = ((lane >> 4) & 1) * 8;

    const uint32_t uQh = smem_u32(sQh), uQl = smem_u32(sQl);
    const uint32_t uKV = smem_u32(sm + 2 * QROWS * QP);

    const int ktiles = 4 * qt + 4;

    // Prologue: Q tile (256x80 hi+lo) + K/V tile 0, one cp.async group
    {
        const size_t qbyte = (bh_off + (size_t)qbase * DP) * 2;
        const char* qh = (const char*)g_Qhi + qbyte;
        const char* ql = (const char*)g_Qlo + qbyte;
#pragma unroll
        for (int it = 0; it < 10; it++) {
            const int id2 = t + it * 512;
            const int arr = id2 / 2560;
            const int rem = id2 - arr * 2560;
            const int row = rem / 10;
            const int c16 = rem - row * 10;
            cp_async16((arr ? uQl : uQh) + (uint32_t)(row * (QP * 2) + c16 * 16),
                       (arr ? ql : qh) + (size_t)row * (DP * 2) + c16 * 16);
        }
        const size_t kbyte = bh_off * 2;
        const char* srcs[4] = {
            (const char*)g_Khi + kbyte, (const char*)g_Klo + kbyte,
            (const char*)g_Vhi + kbyte, (const char*)g_Vlo + kbyte };
#pragma unroll
        for (int it = 0; it < 5; it++) {
            const int id2 = t + it * 512;
            const int arr = id2 / 640;
            const int rem = id2 - arr * 640;
            const int row = rem / 10;
            const int c16 = rem - row * 10;
            cp_async16(uKV + (uint32_t)(arr * (64 * QP * 2) + row * (QP * 2) + c16 * 16),
                       srcs[arr] + (size_t)row * (DP * 2) + c16 * 16);
        }
        cp_commit();
    }

    float oacc[10][4];
#pragma unroll
    for (int nj = 0; nj < 10; nj++)
#pragma unroll
        for (int q = 0; q < 4; q++) oacc[nj][q] = 0.f;
    float m0 = -1e30f, m1 = -1e30f, l0 = 0.f, l1 = 0.f;

    const int gr0 = qbase + wm + g;
    const int gr1 = gr0 + 8;

    for (int kb = 0; kb < ktiles; kb++) {
        if (kb + 1 < ktiles) {
            const size_t kbyte = (bh_off + (size_t)(kb + 1) * 64 * DP) * 2;
            const char* srcs[4] = {
                (const char*)g_Khi + kbyte, (const char*)g_Klo + kbyte,
                (const char*)g_Vhi + kbyte, (const char*)g_Vlo + kbyte };
            const uint32_t dstb = uKV + (uint32_t)(((kb + 1) & 1) * KVSTG * 2);
#pragma unroll
            for (int it = 0; it < 5; it++) {
                const int id2 = t + it * 512;
                const int arr = id2 / 640;
                const int rem = id2 - arr * 640;
                const int row = rem / 10;
                const int c16 = rem - row * 10;
                cp_async16(dstb + (uint32_t)(arr * (64 * QP * 2) + row * (QP * 2) + c16 * 16),
                           srcs[arr] + (size_t)row * (DP * 2) + c16 * 16);
            }
            cp_commit();
            asm volatile("cp.async.wait_group 1;");
        } else {
            asm volatile("cp.async.wait_group 0;");
        }
        __syncthreads();

        const uint32_t stb = uKV + (uint32_t)((kb & 1) * KVSTG * 2);
        const uint32_t uKh = stb;
        const uint32_t uKl = stb + (uint32_t)(64 * QP * 2);
        const uint32_t uVh = stb + (uint32_t)(2 * 64 * QP * 2);
        const uint32_t uVl = stb + (uint32_t)(3 * 64 * QP * 2);

        // S = Q @ K^T
        float sacc[8][4];
#pragma unroll
        for (int ni = 0; ni < 8; ni++)
#pragma unroll
            for (int q = 0; q < 4; q++) sacc[ni][q] = 0.f;

#pragma unroll
        for (int kc = 0; kc < 5; kc++) {
            const int ko = kc * 16;
            uint32_t ah[4], al[4];
            ldsm_x4(ah, uQh + (uint32_t)(((wm + a_r) * QP + ko + a_c) * 2));
            ldsm_x4(al, uQl + (uint32_t)(((wm + a_r) * QP + ko + a_c) * 2));
#pragma unroll
            for (int p = 0; p < 4; p++) {
                const uint32_t off = (uint32_t)(((p * 16 + b_r) * QP + ko + b_c) * 2);
                uint32_t rh[4], rl[4];
                ldsm_x4(rh, uKh + off);
                ldsm_x4(rl, uKl + off);
                mma16816(sacc[2 * p],     ah, rh);
                mma16816(sacc[2 * p + 1], ah, rh + 2);
                mma16816(sacc[2 * p],     ah, rl);
                mma16816(sacc[2 * p + 1], ah, rl + 2);
                mma16816(sacc[2 * p],     al, rh);
                mma16816(sacc[2 * p + 1], al, rh + 2);
            }
        }

        // scale + causal mask (additive -10000, matches reference)
        const bool edge = (kb >= 4 * qt);
#pragma unroll
        for (int ni = 0; ni < 8; ni++) {
#pragma unroll
            for (int q = 0; q < 4; q++) {
                float v = sacc[ni][q] * scale;
                if (edge) {
                    const int key = kb * 64 + ni * 8 + t4 * 2 + (q & 1);
                    const int qr  = (q < 2) ? gr0 : gr1;
                    if (key > qr) v -= 10000.f;
                }
                sacc[ni][q] = v;
            }
        }

        // online softmax
        float mx0 = -1e30f, mx1 = -1e30f;
#pragma unroll
        for (int ni = 0; ni < 8; ni++) {
            mx0 = fmaxf(mx0, fmaxf(sacc[ni][0], sacc[ni][1]));
            mx1 = fmaxf(mx1, fmaxf(sacc[ni][2], sacc[ni][3]));
        }
        mx0 = fmaxf(mx0, __shfl_xor_sync(0xffffffffu, mx0, 1));
        mx0 = fmaxf(mx0, __shfl_xor_sync(0xffffffffu, mx0, 2));
        mx1 = fmaxf(mx1, __shfl_xor_sync(0xffffffffu, mx1, 1));
        mx1 = fmaxf(mx1, __shfl_xor_sync(0xffffffffu, mx1, 2));
        const float mn0 = fmaxf(m0, mx0), mn1 = fmaxf(m1, mx1);
        const float c0 = __expf(m0 - mn0), c1 = __expf(m1 - mn1);
        float s0 = 0.f, s1 = 0.f;
#pragma unroll
        for (int ni = 0; ni < 8; ni++) {
            sacc[ni][0] = __expf(sacc[ni][0] - mn0);
            sacc[ni][1] = __expf(sacc[ni][1] - mn0);
            sacc[ni][2] = __expf(sacc[ni][2] - mn1);
            sacc[ni][3] = __expf(sacc[ni][3] - mn1);
            s0 += sacc[ni][0] + sacc[ni][1];
            s1 += sacc[ni][2] + sacc[ni][3];
        }
        s0 += __shfl_xor_sync(0xffffffffu, s0, 1);
        s0 += __shfl_xor_sync(0xffffffffu, s0, 2);
        s1 += __shfl_xor_sync(0xffffffffu, s1, 1);
        s1 += __shfl_xor_sync(0xffffffffu, s1, 2);
        l0 = l0 * c0 + s0;  m0 = mn0;
        l1 = l1 * c1 + s1;  m1 = mn1;

#pragma unroll
        for (int nj = 0; nj < 10; nj++) {
            oacc[nj][0] *= c0; oacc[nj][1] *= c0;
            oacc[nj][2] *= c1; oacc[nj][3] *= c1;
        }

        // O += P @ V (P in regs; V^T fragments via ldmatrix.trans)
#pragma unroll
        for (int kc2 = 0; kc2 < 4; kc2++) {
            uint32_t aph[4], apl[4];
            split_pack2(sacc[2 * kc2][0],     sacc[2 * kc2][1],     aph[0], apl[0]);
            split_pack2(sacc[2 * kc2][2],     sacc[2 * kc2][3],     aph[1], apl[1]);
            split_pack2(sacc[2 * kc2 + 1][0], sacc[2 * kc2 + 1][1], aph[2], apl[2]);
            split_pack2(sacc[2 * kc2 + 1][2], sacc[2 * kc2 + 1][3], aph[3], apl[3]);
            const int ko2 = kc2 * 16;
#pragma unroll
            for (int p = 0; p < 5; p++) {
                const uint32_t off = (uint32_t)(((ko2 + v_r) * QP + p * 16 + v_c) * 2);
                uint32_t rh[4], rl[4];
                ldsm_x4_t(rh, uVh + off);
                ldsm_x4_t(rl, uVl + off);
                mma16816(oacc[2 * p],     aph, rh);
                mma16816(oacc[2 * p + 1], aph, rh + 2);
                mma16816(oacc[2 * p],     aph, rl);
                mma16816(oacc[2 * p + 1], aph, rl + 2);
                mma16816(oacc[2 * p],     apl, rh);
                mma16816(oacc[2 * p + 1], apl, rh + 2);
            }
        }
        __syncthreads();
    }

    // Normalize and write ctx as bf16 hi/lo split (row-major [MROWS, DD])
    const float inv0 = 1.f / l0, inv1 = 1.f / l1;
    const size_t r0idx = ((size_t)b * SS + qbase + wm + g) * DD + h * DP;
    const size_t r1idx = r0idx + 8 * DD;
#pragma unroll
    for (int nj = 0; nj < 10; nj++) {
        const int col = nj * 8 + t4 * 2;
        uint32_t h0, l0p, h1, l1p;
        split_pack2(oacc[nj][0] * inv0, oacc[nj][1] * inv0, h0, l0p);
        split_pack2(oacc[nj][2] * inv1, oacc[nj][3] * inv1, h1, l1p);
        *(uint32_t*)&g_Chi[r0idx + col] = h0;
        *(uint32_t*)&g_Clo[r0idx + col] = l0p;
        *(uint32_t*)&g_Chi[r1idx + col] = h1;
        *(uint32_t*)&g_Clo[r1idx + col] = l1p;
    }
}

// ---------------------------------------------------------------------------
extern "C" void kernel_launch(void* const* d_in, const int* in_sizes, int n_in,
                              void* d_out, int out_size)
{
    const float* x  = (const float*)d_in[0];
    const float* Wq = (const float*)d_in[2];
    const float* bq = (const float*)d_in[3];
    const float* Wk = (const float*)d_in[4];
    const float* bk = (const float*)d_in[5];
    const float* Wv = (const float*)d_in[6];
    const float* bv = (const float*)d_in[7];
    const float* Wo = (const float*)d_in[8];
    const float* bo = (const float*)d_in[9];
    float* out = (float*)d_out;

    __nv_bfloat16 *xhi, *xlo, *wthi, *wtlo, *chi, *clo;
    cudaGetSymbolAddress((void**)&xhi, g_Xhi);
    cudaGetSymbolAddress((void**)&xlo, g_Xlo);
    cudaGetSymbolAddress((void**)&wthi, g_WThi);
    cudaGetSymbolAddress((void**)&wtlo, g_WTlo);
    cudaGetSymbolAddress((void**)&chi, g_Chi);
    cudaGetSymbolAddress((void**)&clo, g_Clo);

    // 1. split x
    {
        const int n2 = MROWS * DD / 2;
        split_kernel<<<(n2 + 255) / 256, 256>>>(x, xhi, xlo, n2);
    }
    // 2. transpose+split weights (one launch, z selects matrix)
    wsplit4_kernel<<<dim3(40, 40, 4), dim3(32, 8)>>>(Wq, Wk, Wv, Wo);

    // 3. QKV projection (128x64 tiles, 3 CTAs/SM)
    cudaFuncSetAttribute(mma_gemm_kernel, cudaFuncAttributeMaxDynamicSharedMemorySize, GEMM_SMEM_BYTES);
    mma_gemm_kernel<<<dim3(NQKV / 64, MROWS / 128), 256, GEMM_SMEM_BYTES>>>(
        xhi, xlo, wthi, wtlo, bq, bk, bv, 0, nullptr);

    // 4. attention (HMMA flash, double-buffered K/V pipeline)
    cudaFuncSetAttribute(attn_mma_kernel, cudaFuncAttributeMaxDynamicSharedMemorySize, ATT_SMEM_BYTES);
    attn_mma_kernel<<<256, 512, ATT_SMEM_BYTES>>>();

    // 5. output projection (128x64 tiles, 3 CTAs/SM)
    mma_gemm_kernel<<<dim3(DD / 64, MROWS / 128), 256, GEMM_SMEM_BYTES>>>(
        chi, clo, wthi + (size_t)3 * DD * DD, wtlo + (size_t)3 * DD * DD,
        bo, nullptr, nullptr, 1, out);
}

// round 15
// speedup vs baseline: 1.6033x; 1.4704x over previous
#include <cuda_runtime.h>
#include <cuda_fp16.h>
#include <cstdint>
#include <math.h>

// Problem constants
#define BB 2
#define SS 2048
#define DD 1280
#define HH 16
#define DP 80
#define MROWS (BB * SS)          // 4096
#define NQKV (3 * DD)            // 3840

// ---------------------------------------------------------------------------
// Device scratch (allocation-free rule)
// A-side operands: single fp16 plane. B-side operands: fp16 hi+lo planes.
// ---------------------------------------------------------------------------
__device__ __half g_Q[BB * HH * SS * DP];          // single plane
__device__ __half g_Khi[BB * HH * SS * DP];
__device__ __half g_Klo[BB * HH * SS * DP];
__device__ __half g_Vhi[BB * HH * SS * DP];
__device__ __half g_Vlo[BB * HH * SS * DP];

__device__ __half g_X[MROWS * DD];                 // x in fp16 (A side)
__device__ __half g_WThi[4 * DD * DD];             // W^T hi (B side)
__device__ __half g_WTlo[4 * DD * DD];             // W^T lo
__device__ __half g_C[MROWS * DD];                 // ctx fp16 (A side)

// ---------------------------------------------------------------------------
// mma.sync (fp16) + ldmatrix + cp.async helpers (portable to sm_103)
// ---------------------------------------------------------------------------
__device__ __forceinline__ void mma16816h(float* c, const uint32_t* a, const uint32_t* b) {
    asm volatile(
        "mma.sync.aligned.m16n8k16.row.col.f32.f16.f16.f32 "
        "{%0,%1,%2,%3}, {%4,%5,%6,%7}, {%8,%9}, {%0,%1,%2,%3};"
        : "+f"(c[0]), "+f"(c[1]), "+f"(c[2]), "+f"(c[3])
        : "r"(a[0]), "r"(a[1]), "r"(a[2]), "r"(a[3]), "r"(b[0]), "r"(b[1]));
}

__device__ __forceinline__ void ldsm_x4(uint32_t* r, uint32_t addr) {
    asm volatile("ldmatrix.sync.aligned.m8n8.x4.shared.b16 {%0,%1,%2,%3}, [%4];"
        : "=r"(r[0]), "=r"(r[1]), "=r"(r[2]), "=r"(r[3]) : "r"(addr));
}
__device__ __forceinline__ void ldsm_x4_t(uint32_t* r, uint32_t addr) {
    asm volatile("ldmatrix.sync.aligned.m8n8.x4.trans.shared.b16 {%0,%1,%2,%3}, [%4];"
        : "=r"(r[0]), "=r"(r[1]), "=r"(r[2]), "=r"(r[3]) : "r"(addr));
}

__device__ __forceinline__ uint32_t smem_u32(const void* p) {
    return (uint32_t)__cvta_generic_to_shared(p);
}

__device__ __forceinline__ void cp_async16(uint32_t dst, const void* src) {
    asm volatile("cp.async.ca.shared.global [%0], [%1], 16;" :: "r"(dst), "l"(src));
}
__device__ __forceinline__ void cp_commit() {
    asm volatile("cp.async.commit_group;");
}

// pack two floats to fp16x2 (round-to-nearest)
__device__ __forceinline__ uint32_t pack_h2(float a, float b) {
    __half2 h = __floats2half2_rn(a, b);
    return *(uint32_t*)&h;
}

// ---------------------------------------------------------------------------
// fp32 -> fp16 convert (A side, single plane)
// ---------------------------------------------------------------------------
__global__ __launch_bounds__(256) void conv_kernel(const float* __restrict__ src,
                                                   __half* __restrict__ dst, int n2) {
    int i = blockIdx.x * blockDim.x + threadIdx.x;
    if (i >= n2) return;
    float2 v = *(const float2*)(src + 2 * (size_t)i);
    *(__half2*)(dst + 2 * (size_t)i) = __floats2half2_rn(v.x, v.y);
}

// ---------------------------------------------------------------------------
// W [K=1280, N=1280] row-major -> W^T fp16 hi/lo; blockIdx.z selects matrix
// ---------------------------------------------------------------------------
__global__ __launch_bounds__(256) void wsplit4_kernel(const float* __restrict__ W0,
                                                      const float* __restrict__ W1,
                                                      const float* __restrict__ W2,
                                                      const float* __restrict__ W3) {
    __shared__ float tile[32][33];
    const int z  = blockIdx.z;
    const float* W = (z == 0) ? W0 : (z == 1) ? W1 : (z == 2) ? W2 : W3;
    const int ro = z * DD;
    const int tx = threadIdx.x;
    const int ty = threadIdx.y;
    const int n0 = blockIdx.x * 32;
    const int k0 = blockIdx.y * 32;
#pragma unroll
    for (int q = 0; q < 4; q++)
        tile[ty + q * 8][tx] = W[(size_t)(k0 + ty + q * 8) * DD + n0 + tx];
    __syncthreads();
#pragma unroll
    for (int q = 0; q < 4; q++) {
        const int nn = n0 + ty + q * 8;
        const int kk = k0 + tx;
        float v = tile[tx][ty + q * 8];
        __half h = __float2half_rn(v);
        __half l = __float2half_rn(v - __half2float(h));
        g_WThi[(size_t)(ro + nn) * DD + kk] = h;
        g_WTlo[(size_t)(ro + nn) * DD + kk] = l;
    }
}

// ---------------------------------------------------------------------------
// HMMA 2-product fp16 GEMM: C = A @ (Bhi+Blo)^T (+bias)
// 128x64 CTA tile, 8 warps (4m x 2n) of 32x32, 256 threads, 3 CTAs/SM,
// 2-stage cp.async, ldmatrix feeds.
// Stage layout (rows x AP fp16): [0,128) A | [128,192) Bhi | [192,256) Blo
// ---------------------------------------------------------------------------
#define BK2 32
#define AP 40                         // smem pitch fp16 (80B rows)
#define STG256 (256 * AP)             // fp16 per stage
#define GEMM_SMEM_BYTES (2 * STG256 * 2)   // 40960 B

__global__ __launch_bounds__(256, 3) void mma_gemm_kernel(
    const __half* __restrict__ A,
    const __half* __restrict__ Bhi, const __half* __restrict__ Blo,
    const float* __restrict__ b0, const float* __restrict__ b1, const float* __restrict__ b2,
    int mode, float* __restrict__ outp)
{
    extern __shared__ __half dsm[];

    const int t    = threadIdx.x;
    const int wid  = t >> 5;
    const int lane = t & 31;
    const int n0   = blockIdx.x * 64;
    const int m0   = blockIdx.y * 128;
    const int wm   = (wid >> 1) * 32;     // 0,32,64,96
    const int wn   = (wid & 1) * 32;      // 0,32
    const int g    = lane >> 2;
    const int t4   = lane & 3;

    const int a_r = (lane & 7) + ((lane >> 3) & 1) * 8;
    const int a_c = (lane >> 4) * 8;
    const int b_r = (lane & 7) + ((lane >> 4) & 1) * 8;
    const int b_c = ((lane >> 3) & 1) * 8;

    const uint32_t sbase = smem_u32(dsm);

    float acc[2][4][4];
#pragma unroll
    for (int mi = 0; mi < 2; mi++)
#pragma unroll
        for (int ni = 0; ni < 4; ni++)
#pragma unroll
            for (int q = 0; q < 4; q++) acc[mi][ni][q] = 0.f;

    const int KCH = DD / BK2;       // 40

    // loader: 256 rows x 4 x 16B = 1024 ops per chunk (exactly 4 iters of 256)
    // row: [0,128) A | [128,192) Bhi | [192,256) Blo ; reads 32 fp16 per row
#define GEMM_LOAD_CHUNK(kk, sb)                                                \
    {                                                                          \
        _Pragma("unroll")                                                      \
        for (int it = 0; it < 4; it++) {                                       \
            const int idx = t + it * 256;                                      \
            const int row = idx >> 2;                                          \
            const int c16 = idx & 3;                                           \
            const __half* src;                                                 \
            if (row < 128)      src = A   + (size_t)(m0 + row) * DD;           \
            else if (row < 192) src = Bhi + (size_t)(n0 + row - 128) * DD;     \
            else                src = Blo + (size_t)(n0 + row - 192) * DD;     \
            cp_async16((sb) + (uint32_t)(row * (AP * 2) + c16 * 16),           \
                       src + (kk) + c16 * 8);                                  \
        }                                                                      \
        cp_commit();                                                           \
    }

    GEMM_LOAD_CHUNK(0, sbase)

    for (int kc = 0; kc < KCH; kc++) {
        if (kc + 1 < KCH) {
            GEMM_LOAD_CHUNK((kc + 1) * BK2,
                            sbase + (uint32_t)(((kc + 1) & 1) * STG256 * 2))
            asm volatile("cp.async.wait_group 1;");
        } else {
            asm volatile("cp.async.wait_group 0;");
        }
        __syncthreads();

        const uint32_t st = sbase + (uint32_t)((kc & 1) * STG256 * 2);
        const uint32_t uA   = st;
        const uint32_t uBhi = st + 128 * AP * 2;
        const uint32_t uBlo = st + 192 * AP * 2;

#pragma unroll
        for (int ks = 0; ks < 2; ks++) {
            const int kb = ks * 16;
            uint32_t bh[4][2], bl[4][2];
#pragma unroll
            for (int p = 0; p < 2; p++) {
                const uint32_t off = (uint32_t)(((wn + p * 16 + b_r) * AP + kb + b_c) * 2);
                uint32_t r4[4];
                ldsm_x4(r4, uBhi + off);
                bh[2 * p][0] = r4[0]; bh[2 * p][1] = r4[1];
                bh[2 * p + 1][0] = r4[2]; bh[2 * p + 1][1] = r4[3];
                ldsm_x4(r4, uBlo + off);
                bl[2 * p][0] = r4[0]; bl[2 * p][1] = r4[1];
                bl[2 * p + 1][0] = r4[2]; bl[2 * p + 1][1] = r4[3];
            }
#pragma unroll
            for (int mi = 0; mi < 2; mi++) {
                const uint32_t off = (uint32_t)(((wm + mi * 16 + a_r) * AP + kb + a_c) * 2);
                uint32_t ah[4];
                ldsm_x4(ah, uA + off);
#pragma unroll
                for (int ni = 0; ni < 4; ni++) mma16816h(acc[mi][ni], ah, bh[ni]);
#pragma unroll
                for (int ni = 0; ni < 4; ni++) mma16816h(acc[mi][ni], ah, bl[ni]);
            }
        }
        __syncthreads();
    }

    // Epilogue
#pragma unroll
    for (int mi = 0; mi < 2; mi++) {
        const int r0 = m0 + wm + mi * 16 + g;
#pragma unroll
        for (int ni = 0; ni < 4; ni++) {
            const int cg0 = n0 + wn + ni * 8 + t4 * 2;
#pragma unroll
            for (int q = 0; q < 4; q++) {
                const int row = r0 + (q >> 1) * 8;
                const int cg  = cg0 + (q & 1);
                const float v = acc[mi][ni][q];
                if (mode == 0) {
                    const int which = cg / DD;
                    const int cl    = cg - which * DD;
                    const int head  = cl / DP;
                    const int dd    = cl - head * DP;
                    const float val = v + (which == 0 ? b0 : which == 1 ? b1 : b2)[cl];
                    const int b_ = row >> 11;
                    const int s_ = row & 2047;
                    const size_t idx = (((size_t)b_ * HH + head) * SS + s_) * DP + dd;
                    if (which == 0) {
                        g_Q[idx] = __float2half_rn(val);    // A side: single plane
                    } else {
                        __half* dh = (which == 1) ? g_Khi : g_Vhi;
                        __half* dl = (which == 1) ? g_Klo : g_Vlo;
                        __half hv = __float2half_rn(val);
                        dh[idx] = hv;
                        dl[idx] = __float2half_rn(val - __half2float(hv));
                    }
                } else {
                    outp[(size_t)row * DD + cg] = v + b0[cg];
                }
            }
        }
    }
}

// ---------------------------------------------------------------------------
// HMMA 2-product fp16 flash attention: 256 q-rows/CTA, 512 threads,
// 64-key tiles, 2-stage cp.async K/V pipeline. Q single plane; K/V hi+lo.
// ---------------------------------------------------------------------------
#define QP 88                       // smem pitch fp16 (176B rows)
#define QROWS 256
#define KVSTG (4 * 64 * QP)         // fp16 per K/V stage (Kh,Kl,Vh,Vl)
#define ATT_SMEM_BYTES ((QROWS * QP + 2 * KVSTG) * 2)   // 135168 B

__global__ __launch_bounds__(512, 1) void attn_mma_kernel()
{
    extern __shared__ __half sm[];
    __half* sQ = sm;

    const int t    = threadIdx.x;
    const int wid  = t >> 5;
    const int lane = t & 31;
    const int g    = lane >> 2;
    const int t4   = lane & 3;
    const int idx   = blockIdx.x;            // 0..255
    const int qt    = 7 - (idx >> 5);        // 8 q-tiles, big first
    const int hb    = idx & 31;
    const int h     = hb & 15;
    const int b     = hb >> 4;
    const size_t bh_off = ((size_t)b * HH + h) * SS * DP;
    const int qbase = qt * QROWS;
    const int wm    = wid * 16;
    const float scale = 0.11180339887498948f;   // 1/sqrt(80)

    const int a_r = (lane & 7) + ((lane >> 3) & 1) * 8;
    const int a_c = (lane >> 4) * 8;
    const int b_r = (lane & 7) + ((lane >> 4) & 1) * 8;
    const int b_c = ((lane >> 3) & 1) * 8;
    const int v_r = (lane & 7) + ((lane >> 3) & 1) * 8;
    const int v_c = ((lane >> 4) & 1) * 8;

    const uint32_t uQ  = smem_u32(sQ);
    const uint32_t uKV = smem_u32(sm + QROWS * QP);

    const int ktiles = 4 * qt + 4;

    // Prologue: Q tile (256x80 fp16) + K/V tile 0, one cp.async group
    {
        const char* qsrc = (const char*)g_Q + (bh_off + (size_t)qbase * DP) * 2;
#pragma unroll
        for (int it = 0; it < 5; it++) {
            const int id2 = t + it * 512;          // 0..2559
            const int row = id2 / 10;
            const int c16 = id2 - row * 10;
            cp_async16(uQ + (uint32_t)(row * (QP * 2) + c16 * 16),
                       qsrc + (size_t)row * (DP * 2) + c16 * 16);
        }
        const size_t kbyte = bh_off * 2;
        const char* srcs[4] = {
            (const char*)g_Khi + kbyte, (const char*)g_Klo + kbyte,
            (const char*)g_Vhi + kbyte, (const char*)g_Vlo + kbyte };
#pragma unroll
        for (int it = 0; it < 5; it++) {
            const int id2 = t + it * 512;          // 0..2559
            const int arr = id2 / 640;
            const int rem = id2 - arr * 640;
            const int row = rem / 10;
            const int c16 = rem - row * 10;
            cp_async16(uKV + (uint32_t)(arr * (64 * QP * 2) + row * (QP * 2) + c16 * 16),
                       srcs[arr] + (size_t)row * (DP * 2) + c16 * 16);
        }
        cp_commit();
    }

    float oacc[10][4];
#pragma unroll
    for (int nj = 0; nj < 10; nj++)
#pragma unroll
        for (int q = 0; q < 4; q++) oacc[nj][q] = 0.f;
    float m0 = -1e30f, m1 = -1e30f, l0 = 0.f, l1 = 0.f;

    const int gr0 = qbase + wm + g;
    const int gr1 = gr0 + 8;

    for (int kb = 0; kb < ktiles; kb++) {
        if (kb + 1 < ktiles) {
            const size_t kbyte = (bh_off + (size_t)(kb + 1) * 64 * DP) * 2;
            const char* srcs[4] = {
                (const char*)g_Khi + kbyte, (const char*)g_Klo + kbyte,
                (const char*)g_Vhi + kbyte, (const char*)g_Vlo + kbyte };
            const uint32_t dstb = uKV + (uint32_t)(((kb + 1) & 1) * KVSTG * 2);
#pragma unroll
            for (int it = 0; it < 5; it++) {
                const int id2 = t + it * 512;
                const int arr = id2 / 640;
                const int rem = id2 - arr * 640;
                const int row = rem / 10;
                const int c16 = rem - row * 10;
                cp_async16(dstb + (uint32_t)(arr * (64 * QP * 2) + row * (QP * 2) + c16 * 16),
                           srcs[arr] + (size_t)row * (DP * 2) + c16 * 16);
            }
            cp_commit();
            asm volatile("cp.async.wait_group 1;");
        } else {
            asm volatile("cp.async.wait_group 0;");
        }
        __syncthreads();

        const uint32_t stb = uKV + (uint32_t)((kb & 1) * KVSTG * 2);
        const uint32_t uKh = stb;
        const uint32_t uKl = stb + (uint32_t)(64 * QP * 2);
        const uint32_t uVh = stb + (uint32_t)(2 * 64 * QP * 2);
        const uint32_t uVl = stb + (uint32_t)(3 * 64 * QP * 2);

        // S = Q @ (Khi+Klo)^T   (2-product: Qh x hi + Qh x lo)
        float sacc[8][4];
#pragma unroll
        for (int ni = 0; ni < 8; ni++)
#pragma unroll
            for (int q = 0; q < 4; q++) sacc[ni][q] = 0.f;

#pragma unroll
        for (int kc = 0; kc < 5; kc++) {
            const int ko = kc * 16;
            uint32_t ah[4];
            ldsm_x4(ah, uQ + (uint32_t)(((wm + a_r) * QP + ko + a_c) * 2));
#pragma unroll
            for (int p = 0; p < 4; p++) {
                const uint32_t off = (uint32_t)(((p * 16 + b_r) * QP + ko + b_c) * 2);
                uint32_t rh[4], rl[4];
                ldsm_x4(rh, uKh + off);
                ldsm_x4(rl, uKl + off);
                mma16816h(sacc[2 * p],     ah, rh);
                mma16816h(sacc[2 * p + 1], ah, rh + 2);
                mma16816h(sacc[2 * p],     ah, rl);
                mma16816h(sacc[2 * p + 1], ah, rl + 2);
            }
        }

        // scale + causal mask (additive -10000, matches reference)
        const bool edge = (kb >= 4 * qt);
#pragma unroll
        for (int ni = 0; ni < 8; ni++) {
#pragma unroll
            for (int q = 0; q < 4; q++) {
                float v = sacc[ni][q] * scale;
                if (edge) {
                    const int key = kb * 64 + ni * 8 + t4 * 2 + (q & 1);
                    const int qr  = (q < 2) ? gr0 : gr1;
                    if (key > qr) v -= 10000.f;
                }
                sacc[ni][q] = v;
            }
        }

        // online softmax
        float mx0 = -1e30f, mx1 = -1e30f;
#pragma unroll
        for (int ni = 0; ni < 8; ni++) {
            mx0 = fmaxf(mx0, fmaxf(sacc[ni][0], sacc[ni][1]));
            mx1 = fmaxf(mx1, fmaxf(sacc[ni][2], sacc[ni][3]));
        }
        mx0 = fmaxf(mx0, __shfl_xor_sync(0xffffffffu, mx0, 1));
        mx0 = fmaxf(mx0, __shfl_xor_sync(0xffffffffu, mx0, 2));
        mx1 = fmaxf(mx1, __shfl_xor_sync(0xffffffffu, mx1, 1));
        mx1 = fmaxf(mx1, __shfl_xor_sync(0xffffffffu, mx1, 2));
        const float mn0 = fmaxf(m0, mx0), mn1 = fmaxf(m1, mx1);
        const float c0 = __expf(m0 - mn0), c1 = __expf(m1 - mn1);
        float s0 = 0.f, s1 = 0.f;
#pragma unroll
        for (int ni = 0; ni < 8; ni++) {
            sacc[ni][0] = __expf(sacc[ni][0] - mn0);
            sacc[ni][1] = __expf(sacc[ni][1] - mn0);
            sacc[ni][2] = __expf(sacc[ni][2] - mn1);
            sacc[ni][3] = __expf(sacc[ni][3] - mn1);
            s0 += sacc[ni][0] + sacc[ni][1];
            s1 += sacc[ni][2] + sacc[ni][3];
        }
        s0 += __shfl_xor_sync(0xffffffffu, s0, 1);
        s0 += __shfl_xor_sync(0xffffffffu, s0, 2);
        s1 += __shfl_xor_sync(0xffffffffu, s1, 1);
        s1 += __shfl_xor_sync(0xffffffffu, s1, 2);
        l0 = l0 * c0 + s0;  m0 = mn0;
        l1 = l1 * c1 + s1;  m1 = mn1;

#pragma unroll
        for (int nj = 0; nj < 10; nj++) {
            oacc[nj][0] *= c0; oacc[nj][1] *= c0;
            oacc[nj][2] *= c1; oacc[nj][3] *= c1;
        }

        // O += P @ (Vhi+Vlo)  (P packed to fp16 single plane)
#pragma unroll
        for (int kc2 = 0; kc2 < 4; kc2++) {
            uint32_t aph[4];
            aph[0] = pack_h2(sacc[2 * kc2][0],     sacc[2 * kc2][1]);
            aph[1] = pack_h2(sacc[2 * kc2][2],     sacc[2 * kc2][3]);
            aph[2] = pack_h2(sacc[2 * kc2 + 1][0], sacc[2 * kc2 + 1][1]);
            aph[3] = pack_h2(sacc[2 * kc2 + 1][2], sacc[2 * kc2 + 1][3]);
            const int ko2 = kc2 * 16;
#pragma unroll
            for (int p = 0; p < 5; p++) {
                const uint32_t off = (uint32_t)(((ko2 + v_r) * QP + p * 16 + v_c) * 2);
                uint32_t rh[4], rl[4];
                ldsm_x4_t(rh, uVh + off);
                ldsm_x4_t(rl, uVl + off);
                mma16816h(oacc[2 * p],     aph, rh);
                mma16816h(oacc[2 * p + 1], aph, rh + 2);
                mma16816h(oacc[2 * p],     aph, rl);
                mma16816h(oacc[2 * p + 1], aph, rl + 2);
            }
        }
        __syncthreads();
    }

    // Normalize and write ctx as single fp16 plane (row-major [MROWS, DD])
    const float inv0 = 1.f / l0, inv1 = 1.f / l1;
    const size_t r0idx = ((size_t)b * SS + qbase + wm + g) * DD + h * DP;
    const size_t r1idx = r0idx + 8 * DD;
#pragma unroll
    for (int nj = 0; nj < 10; nj++) {
        const int col = nj * 8 + t4 * 2;
        *(uint32_t*)&g_C[r0idx + col] = pack_h2(oacc[nj][0] * inv0, oacc[nj][1] * inv0);
        *(uint32_t*)&g_C[r1idx + col] = pack_h2(oacc[nj][2] * inv1, oacc[nj][3] * inv1);
    }
}

// ---------------------------------------------------------------------------
extern "C" void kernel_launch(void* const* d_in, const int* in_sizes, int n_in,
                              void* d_out, int out_size)
{
    const float* x  = (const float*)d_in[0];
    const float* Wq = (const float*)d_in[2];
    const float* bq = (const float*)d_in[3];
    const float* Wk = (const float*)d_in[4];
    const float* bk = (const float*)d_in[5];
    const float* Wv = (const float*)d_in[6];
    const float* bv = (const float*)d_in[7];
    const float* Wo = (const float*)d_in[8];
    const float* bo = (const float*)d_in[9];
    float* out = (float*)d_out;

    __half *xp, *wthi, *wtlo, *cp;
    cudaGetSymbolAddress((void**)&xp, g_X);
    cudaGetSymbolAddress((void**)&wthi, g_WThi);
    cudaGetSymbolAddress((void**)&wtlo, g_WTlo);
    cudaGetSymbolAddress((void**)&cp, g_C);

    // 1. convert x to fp16
    {
        const int n2 = MROWS * DD / 2;
        conv_kernel<<<(n2 + 255) / 256, 256>>>(x, xp, n2);
    }
    // 2. transpose+split weights (fp16 hi/lo)
    wsplit4_kernel<<<dim3(40, 40, 4), dim3(32, 8)>>>(Wq, Wk, Wv, Wo);

    // 3. QKV projection (2-product fp16)
    cudaFuncSetAttribute(mma_gemm_kernel, cudaFuncAttributeMaxDynamicSharedMemorySize, GEMM_SMEM_BYTES);
    mma_gemm_kernel<<<dim3(NQKV / 64, MROWS / 128), 256, GEMM_SMEM_BYTES>>>(
        xp, wthi, wtlo, bq, bk, bv, 0, nullptr);

    // 4. attention (2-product fp16 flash)
    cudaFuncSetAttribute(attn_mma_kernel, cudaFuncAttributeMaxDynamicSharedMemorySize, ATT_SMEM_BYTES);
    attn_mma_kernel<<<256, 512, ATT_SMEM_BYTES>>>();

    // 5. output projection (2-product fp16)
    mma_gemm_kernel<<<dim3(DD / 64, MROWS / 128), 256, GEMM_SMEM_BYTES>>>(
        cp, wthi + (size_t)3 * DD * DD, wtlo + (size_t)3 * DD * DD,
        bo, nullptr, nullptr, 1, out);
}

// round 17
// speedup vs baseline: 2.2830x; 1.4239x over previous
#include <cuda_runtime.h>
#include <cuda_fp16.h>
#include <cstdint>
#include <math.h>

// Problem constants
#define BB 2
#define SS 2048
#define DD 1280
#define HH 16
#define DP 80
#define MROWS (BB * SS)          // 4096
#define NQKV (3 * DD)            // 3840

// ---------------------------------------------------------------------------
// Device scratch (allocation-free rule). Everything single-plane fp16.
// ---------------------------------------------------------------------------
__device__ __half g_Q[BB * HH * SS * DP];
__device__ __half g_K[BB * HH * SS * DP];
__device__ __half g_V[BB * HH * SS * DP];
__device__ __half g_X[MROWS * DD];
__device__ __half g_WT[4 * DD * DD];       // rows [0,3840)=Wq,Wk,Wv^T ; [3840,5120)=Wo^T
__device__ __half g_C[MROWS * DD];

// ---------------------------------------------------------------------------
// mma.sync (fp16) + ldmatrix + cp.async helpers (portable to sm_103)
// ---------------------------------------------------------------------------
__device__ __forceinline__ void mma16816h(float* c, const uint32_t* a, const uint32_t* b) {
    asm volatile(
        "mma.sync.aligned.m16n8k16.row.col.f32.f16.f16.f32 "
        "{%0,%1,%2,%3}, {%4,%5,%6,%7}, {%8,%9}, {%0,%1,%2,%3};"
        : "+f"(c[0]), "+f"(c[1]), "+f"(c[2]), "+f"(c[3])
        : "r"(a[0]), "r"(a[1]), "r"(a[2]), "r"(a[3]), "r"(b[0]), "r"(b[1]));
}

__device__ __forceinline__ void ldsm_x4(uint32_t* r, uint32_t addr) {
    asm volatile("ldmatrix.sync.aligned.m8n8.x4.shared.b16 {%0,%1,%2,%3}, [%4];"
        : "=r"(r[0]), "=r"(r[1]), "=r"(r[2]), "=r"(r[3]) : "r"(addr));
}
__device__ __forceinline__ void ldsm_x4_t(uint32_t* r, uint32_t addr) {
    asm volatile("ldmatrix.sync.aligned.m8n8.x4.trans.shared.b16 {%0,%1,%2,%3}, [%4];"
        : "=r"(r[0]), "=r"(r[1]), "=r"(r[2]), "=r"(r[3]) : "r"(addr));
}

__device__ __forceinline__ uint32_t smem_u32(const void* p) {
    return (uint32_t)__cvta_generic_to_shared(p);
}

__device__ __forceinline__ void cp_async16(uint32_t dst, const void* src) {
    asm volatile("cp.async.ca.shared.global [%0], [%1], 16;" :: "r"(dst), "l"(src));
}
__device__ __forceinline__ void cp_commit() {
    asm volatile("cp.async.commit_group;");
}

__device__ __forceinline__ uint32_t pack_h2(float a, float b) {
    __half2 h = __floats2half2_rn(a, b);
    return *(uint32_t*)&h;
}

// ---------------------------------------------------------------------------
// fp32 -> fp16 convert
// ---------------------------------------------------------------------------
__global__ __launch_bounds__(256) void conv_kernel(const float* __restrict__ src,
                                                   __half* __restrict__ dst, int n2) {
    int i = blockIdx.x * blockDim.x + threadIdx.x;
    if (i >= n2) return;
    float2 v = *(const float2*)(src + 2 * (size_t)i);
    *(__half2*)(dst + 2 * (size_t)i) = __floats2half2_rn(v.x, v.y);
}

// ---------------------------------------------------------------------------
// W [K=1280, N=1280] row-major -> W^T fp16; blockIdx.z selects matrix
// ---------------------------------------------------------------------------
__global__ __launch_bounds__(256) void wsplit4_kernel(const float* __restrict__ W0,
                                                      const float* __restrict__ W1,
                                                      const float* __restrict__ W2,
                                                      const float* __restrict__ W3) {
    __shared__ float tile[32][33];
    const int z  = blockIdx.z;
    const float* W = (z == 0) ? W0 : (z == 1) ? W1 : (z == 2) ? W2 : W3;
    const int ro = z * DD;
    const int tx = threadIdx.x;
    const int ty = threadIdx.y;
    const int n0 = blockIdx.x * 32;
    const int k0 = blockIdx.y * 32;
#pragma unroll
    for (int q = 0; q < 4; q++)
        tile[ty + q * 8][tx] = W[(size_t)(k0 + ty + q * 8) * DD + n0 + tx];
    __syncthreads();
#pragma unroll
    for (int q = 0; q < 4; q++) {
        const int nn = n0 + ty + q * 8;
        const int kk = k0 + tx;
        g_WT[(size_t)(ro + nn) * DD + kk] = __float2half_rn(tile[tx][ty + q * 8]);
    }
}

// ---------------------------------------------------------------------------
// HMMA fp16 GEMM (single product): C = A @ B^T (+bias)
// 128x64 CTA tile, 8 warps (4m x 2n) of 32x32, 256 threads, 3 CTAs/SM,
// 2-stage cp.async, ldmatrix feeds.
// Stage layout (rows x AP fp16): [0,128) A | [128,192) B
// ---------------------------------------------------------------------------
#define BK2 32
#define AP 40                         // smem pitch fp16 (80B rows)
#define STG192 (192 * AP)             // fp16 per stage
#define GEMM_SMEM_BYTES (2 * STG192 * 2)   // 30720 B

__global__ __launch_bounds__(256, 3) void mma_gemm_kernel(
    const __half* __restrict__ A, const __half* __restrict__ B,
    const float* __restrict__ b0, const float* __restrict__ b1, const float* __restrict__ b2,
    int mode, float* __restrict__ outp)
{
    extern __shared__ __half dsm[];

    const int t    = threadIdx.x;
    const int wid  = t >> 5;
    const int lane = t & 31;
    const int n0   = blockIdx.x * 64;
    const int m0   = blockIdx.y * 128;
    const int wm   = (wid >> 1) * 32;     // 0,32,64,96
    const int wn   = (wid & 1) * 32;      // 0,32
    const int g    = lane >> 2;
    const int t4   = lane & 3;

    const int a_r = (lane & 7) + ((lane >> 3) & 1) * 8;
    const int a_c = (lane >> 4) * 8;
    const int b_r = (lane & 7) + ((lane >> 4) & 1) * 8;
    const int b_c = ((lane >> 3) & 1) * 8;

    const uint32_t sbase = smem_u32(dsm);

    float acc[2][4][4];
#pragma unroll
    for (int mi = 0; mi < 2; mi++)
#pragma unroll
        for (int ni = 0; ni < 4; ni++)
#pragma unroll
            for (int q = 0; q < 4; q++) acc[mi][ni][q] = 0.f;

    const int KCH = DD / BK2;       // 40

    // loader: 192 rows x 4 x 16B = 768 ops per chunk (3 iters of 256)
#define GEMM_LOAD_CHUNK(kk, sb)                                                \
    {                                                                          \
        _Pragma("unroll")                                                      \
        for (int it = 0; it < 3; it++) {                                       \
            const int idx = t + it * 256;                                      \
            const int row = idx >> 2;                                          \
            const int c16 = idx & 3;                                           \
            const __half* src = (row < 128)                                    \
                ? A + (size_t)(m0 + row) * DD                                  \
                : B + (size_t)(n0 + row - 128) * DD;                           \
            cp_async16((sb) + (uint32_t)(row * (AP * 2) + c16 * 16),           \
                       src + (kk) + c16 * 8);                                  \
        }                                                                      \
        cp_commit();                                                           \
    }

    GEMM_LOAD_CHUNK(0, sbase)

    for (int kc = 0; kc < KCH; kc++) {
        if (kc + 1 < KCH) {
            GEMM_LOAD_CHUNK((kc + 1) * BK2,
                            sbase + (uint32_t)(((kc + 1) & 1) * STG192 * 2))
            asm volatile("cp.async.wait_group 1;");
        } else {
            asm volatile("cp.async.wait_group 0;");
        }
        __syncthreads();

        const uint32_t st = sbase + (uint32_t)((kc & 1) * STG192 * 2);
        const uint32_t uA = st;
        const uint32_t uB = st + 128 * AP * 2;

#pragma unroll
        for (int ks = 0; ks < 2; ks++) {
            const int kb = ks * 16;
            uint32_t bh[4][2];
#pragma unroll
            for (int p = 0; p < 2; p++) {
                const uint32_t off = (uint32_t)(((wn + p * 16 + b_r) * AP + kb + b_c) * 2);
                uint32_t r4[4];
                ldsm_x4(r4, uB + off);
                bh[2 * p][0] = r4[0]; bh[2 * p][1] = r4[1];
                bh[2 * p + 1][0] = r4[2]; bh[2 * p + 1][1] = r4[3];
            }
#pragma unroll
            for (int mi = 0; mi < 2; mi++) {
                const uint32_t off = (uint32_t)(((wm + mi * 16 + a_r) * AP + kb + a_c) * 2);
                uint32_t ah[4];
                ldsm_x4(ah, uA + off);
#pragma unroll
                for (int ni = 0; ni < 4; ni++) mma16816h(acc[mi][ni], ah, bh[ni]);
            }
        }
        __syncthreads();
    }

    // Epilogue
#pragma unroll
    for (int mi = 0; mi < 2; mi++) {
        const int r0 = m0 + wm + mi * 16 + g;
#pragma unroll
        for (int ni = 0; ni < 4; ni++) {
            const int cg0 = n0 + wn + ni * 8 + t4 * 2;
#pragma unroll
            for (int q = 0; q < 4; q++) {
                const int row = r0 + (q >> 1) * 8;
                const int cg  = cg0 + (q & 1);
                const float v = acc[mi][ni][q];
                if (mode == 0) {
                    const int which = cg / DD;
                    const int cl    = cg - which * DD;
                    const int head  = cl / DP;
                    const int dd    = cl - head * DP;
                    const float val = v + (which == 0 ? b0 : which == 1 ? b1 : b2)[cl];
                    __half* dst = (which == 0) ? g_Q : (which == 1) ? g_K : g_V;
                    const int b_ = row >> 11;
                    const int s_ = row & 2047;
                    dst[(((size_t)b_ * HH + head) * SS + s_) * DP + dd] = __float2half_rn(val);
                } else {
                    outp[(size_t)row * DD + cg] = v + b0[cg];
                }
            }
        }
    }
}

// ---------------------------------------------------------------------------
// HMMA fp16 flash attention (single product): 256 q-rows/CTA, 512 threads,
// 64-key tiles, 2-stage cp.async K/V pipeline. All operands single plane.
// ---------------------------------------------------------------------------
#define QP 88                       // smem pitch fp16 (176B rows)
#define QROWS 256
#define KVSTG (2 * 64 * QP)         // fp16 per K/V stage (K, V)
#define ATT_SMEM_BYTES ((QROWS * QP + 2 * KVSTG) * 2)   // 90112 B

__global__ __launch_bounds__(512, 1) void attn_mma_kernel()
{
    extern __shared__ __half sm[];
    __half* sQ = sm;

    const int t    = threadIdx.x;
    const int wid  = t >> 5;
    const int lane = t & 31;
    const int g    = lane >> 2;
    const int t4   = lane & 3;
    const int idx   = blockIdx.x;            // 0..255
    const int qt    = 7 - (idx >> 5);        // 8 q-tiles, big first
    const int hb    = idx & 31;
    const int h     = hb & 15;
    const int b     = hb >> 4;
    const size_t bh_off = ((size_t)b * HH + h) * SS * DP;
    const int qbase = qt * QROWS;
    const int wm    = wid * 16;
    const float scale = 0.11180339887498948f;   // 1/sqrt(80)

    const int a_r = (lane & 7) + ((lane >> 3) & 1) * 8;
    const int a_c = (lane >> 4) * 8;
    const int b_r = (lane & 7) + ((lane >> 4) & 1) * 8;
    const int b_c = ((lane >> 3) & 1) * 8;
    const int v_r = (lane & 7) + ((lane >> 3) & 1) * 8;
    const int v_c = ((lane >> 4) & 1) * 8;

    const uint32_t uQ  = smem_u32(sQ);
    const uint32_t uKV = smem_u32(sm + QROWS * QP);

    const int ktiles = 4 * qt + 4;

    // K/V tile loader: 2 arrays x 64 rows x 10 x 16B = 1280 ops
#define ATT_LOAD_KV(kbq, dstb)                                                  \
    {                                                                           \
        const size_t kbyte = (bh_off + (size_t)(kbq) * 64 * DP) * 2;            \
        const char* srcs[2] = { (const char*)g_K + kbyte,                       \
                                (const char*)g_V + kbyte };                     \
        _Pragma("unroll")                                                       \
        for (int it = 0; it < 3; it++) {                                        \
            const int id2 = t + it * 512;                                       \
            if (id2 < 1280) {                                                   \
                const int arr = id2 / 640;                                      \
                const int rem = id2 - arr * 640;                                \
                const int row = rem / 10;                                       \
                const int c16 = rem - row * 10;                                 \
                cp_async16((dstb) + (uint32_t)(arr * (64 * QP * 2)              \
                               + row * (QP * 2) + c16 * 16),                    \
                           srcs[arr] + (size_t)row * (DP * 2) + c16 * 16);      \
            }                                                                   \
        }                                                                       \
        cp_commit();                                                            \
    }

    // Prologue: Q tile (256x80 fp16) + K/V tile 0 in one group
    {
        const char* qsrc = (const char*)g_Q + (bh_off + (size_t)qbase * DP) * 2;
#pragma unroll
        for (int it = 0; it < 5; it++) {
            const int id2 = t + it * 512;          // 0..2559
            const int row = id2 / 10;
            const int c16 = id2 - row * 10;
            cp_async16(uQ + (uint32_t)(row * (QP * 2) + c16 * 16),
                       qsrc + (size_t)row * (DP * 2) + c16 * 16);
        }
        ATT_LOAD_KV(0, uKV)
    }

    float oacc[10][4];
#pragma unroll
    for (int nj = 0; nj < 10; nj++)
#pragma unroll
        for (int q = 0; q < 4; q++) oacc[nj][q] = 0.f;
    float m0 = -1e30f, m1 = -1e30f, l0 = 0.f, l1 = 0.f;

    const int gr0 = qbase + wm + g;
    const int gr1 = gr0 + 8;

    for (int kb = 0; kb < ktiles; kb++) {
        if (kb + 1 < ktiles) {
            ATT_LOAD_KV(kb + 1, uKV + (uint32_t)(((kb + 1) & 1) * KVSTG * 2))
            asm volatile("cp.async.wait_group 1;");
        } else {
            asm volatile("cp.async.wait_group 0;");
        }
        __syncthreads();

        const uint32_t stb = uKV + (uint32_t)((kb & 1) * KVSTG * 2);
        const uint32_t uK = stb;
        const uint32_t uV = stb + (uint32_t)(64 * QP * 2);

        // S = Q @ K^T
        float sacc[8][4];
#pragma unroll
        for (int ni = 0; ni < 8; ni++)
#pragma unroll
            for (int q = 0; q < 4; q++) sacc[ni][q] = 0.f;

#pragma unroll
        for (int kc = 0; kc < 5; kc++) {
            const int ko = kc * 16;
            uint32_t ah[4];
            ldsm_x4(ah, uQ + (uint32_t)(((wm + a_r) * QP + ko + a_c) * 2));
#pragma unroll
            for (int p = 0; p < 4; p++) {
                const uint32_t off = (uint32_t)(((p * 16 + b_r) * QP + ko + b_c) * 2);
                uint32_t rh[4];
                ldsm_x4(rh, uK + off);
                mma16816h(sacc[2 * p],     ah, rh);
                mma16816h(sacc[2 * p + 1], ah, rh + 2);
            }
        }

        // scale + causal mask (additive -10000, matches reference)
        const bool edge = (kb >= 4 * qt);
#pragma unroll
        for (int ni = 0; ni < 8; ni++) {
#pragma unroll
            for (int q = 0; q < 4; q++) {
                float v = sacc[ni][q] * scale;
                if (edge) {
                    const int key = kb * 64 + ni * 8 + t4 * 2 + (q & 1);
                    const int qr  = (q < 2) ? gr0 : gr1;
                    if (key > qr) v -= 10000.f;
                }
                sacc[ni][q] = v;
            }
        }

        // online softmax
        float mx0 = -1e30f, mx1 = -1e30f;
#pragma unroll
        for (int ni = 0; ni < 8; ni++) {
            mx0 = fmaxf(mx0, fmaxf(sacc[ni][0], sacc[ni][1]));
            mx1 = fmaxf(mx1, fmaxf(sacc[ni][2], sacc[ni][3]));
        }
        mx0 = fmaxf(mx0, __shfl_xor_sync(0xffffffffu, mx0, 1));
        mx0 = fmaxf(mx0, __shfl_xor_sync(0xffffffffu, mx0, 2));
        mx1 = fmaxf(mx1, __shfl_xor_sync(0xffffffffu, mx1, 1));
        mx1 = fmaxf(mx1, __shfl_xor_sync(0xffffffffu, mx1, 2));
        const float mn0 = fmaxf(m0, mx0), mn1 = fmaxf(m1, mx1);
        const float c0 = __expf(m0 - mn0), c1 = __expf(m1 - mn1);
        float s0 = 0.f, s1 = 0.f;
#pragma unroll
        for (int ni = 0; ni < 8; ni++) {
            sacc[ni][0] = __expf(sacc[ni][0] - mn0);
            sacc[ni][1] = __expf(sacc[ni][1] - mn0);
            sacc[ni][2] = __expf(sacc[ni][2] - mn1);
            sacc[ni][3] = __expf(sacc[ni][3] - mn1);
            s0 += sacc[ni][0] + sacc[ni][1];
            s1 += sacc[ni][2] + sacc[ni][3];
        }
        s0 += __shfl_xor_sync(0xffffffffu, s0, 1);
        s0 += __shfl_xor_sync(0xffffffffu, s0, 2);
        s1 += __shfl_xor_sync(0xffffffffu, s1, 1);
        s1 += __shfl_xor_sync(0xffffffffu, s1, 2);
        l0 = l0 * c0 + s0;  m0 = mn0;
        l1 = l1 * c1 + s1;  m1 = mn1;

#pragma unroll
        for (int nj = 0; nj < 10; nj++) {
            oacc[nj][0] *= c0; oacc[nj][1] *= c0;
            oacc[nj][2] *= c1; oacc[nj][3] *= c1;
        }

        // O += P @ V  (P packed to fp16)
#pragma unroll
        for (int kc2 = 0; kc2 < 4; kc2++) {
            uint32_t aph[4];
            aph[0] = pack_h2(sacc[2 * kc2][0],     sacc[2 * kc2][1]);
            aph[1] = pack_h2(sacc[2 * kc2][2],     sacc[2 * kc2][3]);
            aph[2] = pack_h2(sacc[2 * kc2 + 1][0], sacc[2 * kc2 + 1][1]);
            aph[3] = pack_h2(sacc[2 * kc2 + 1][2], sacc[2 * kc2 + 1][3]);
            const int ko2 = kc2 * 16;
#pragma unroll
            for (int p = 0; p < 5; p++) {
                const uint32_t off = (uint32_t)(((ko2 + v_r) * QP + p * 16 + v_c) * 2);
                uint32_t rh[4];
                ldsm_x4_t(rh, uV + off);
                mma16816h(oacc[2 * p],     aph, rh);
                mma16816h(oacc[2 * p + 1], aph, rh + 2);
            }
        }
        __syncthreads();
    }

    // Normalize and write ctx as fp16 (row-major [MROWS, DD])
    const float inv0 = 1.f / l0, inv1 = 1.f / l1;
    const size_t r0idx = ((size_t)b * SS + qbase + wm + g) * DD + h * DP;
    const size_t r1idx = r0idx + 8 * DD;
#pragma unroll
    for (int nj = 0; nj < 10; nj++) {
        const int col = nj * 8 + t4 * 2;
        *(uint32_t*)&g_C[r0idx + col] = pack_h2(oacc[nj][0] * inv0, oacc[nj][1] * inv0);
        *(uint32_t*)&g_C[r1idx + col] = pack_h2(oacc[nj][2] * inv1, oacc[nj][3] * inv1);
    }
}

// ---------------------------------------------------------------------------
extern "C" void kernel_launch(void* const* d_in, const int* in_sizes, int n_in,
                              void* d_out, int out_size)
{
    const float* x  = (const float*)d_in[0];
    const float* Wq = (const float*)d_in[2];
    const float* bq = (const float*)d_in[3];
    const float* Wk = (const float*)d_in[4];
    const float* bk = (const float*)d_in[5];
    const float* Wv = (const float*)d_in[6];
    const float* bv = (const float*)d_in[7];
    const float* Wo = (const float*)d_in[8];
    const float* bo = (const float*)d_in[9];
    float* out = (float*)d_out;

    __half *xp, *wt, *cp;
    cudaGetSymbolAddress((void**)&xp, g_X);
    cudaGetSymbolAddress((void**)&wt, g_WT);
    cudaGetSymbolAddress((void**)&cp, g_C);

    // 1. convert x to fp16
    {
        const int n2 = MROWS * DD / 2;
        conv_kernel<<<(n2 + 255) / 256, 256>>>(x, xp, n2);
    }
    // 2. transpose weights to fp16 W^T
    wsplit4_kernel<<<dim3(40, 40, 4), dim3(32, 8)>>>(Wq, Wk, Wv, Wo);

    // 3. QKV projection (single-product fp16)
    cudaFuncSetAttribute(mma_gemm_kernel, cudaFuncAttributeMaxDynamicSharedMemorySize, GEMM_SMEM_BYTES);
    mma_gemm_kernel<<<dim3(NQKV / 64, MROWS / 128), 256, GEMM_SMEM_BYTES>>>(
        xp, wt, bq, bk, bv, 0, nullptr);

    // 4. attention (single-product fp16 flash)
    cudaFuncSetAttribute(attn_mma_kernel, cudaFuncAttributeMaxDynamicSharedMemorySize, ATT_SMEM_BYTES);
    attn_mma_kernel<<<256, 512, ATT_SMEM_BYTES>>>();

    // 5. output projection (single-product fp16)
    mma_gemm_kernel<<<dim3(DD / 64, MROWS / 128), 256, GEMM_SMEM_BYTES>>>(
        cp, wt + (size_t)3 * DD * DD, bo, nullptr, nullptr, 1, out);
}